// round 1
// baseline (speedup 1.0000x reference)
#include <cuda_runtime.h>
#include <cstdint>

// Shapes (fixed): B=8, H=W=32, C=256 -> NTOK=8192 tokens, C2=128, HW=1024,
// dense-gate K = HW*C = 262144.

__device__ float g_theta[8192 * 128];
__device__ float g_phi[8192 * 128];
__device__ float g_alpha[8192 * 128];
__device__ float g_S[(size_t)8192 * 8192];   // 256 MB attention scratch
__device__ float g_av[8192 * 128];
__device__ float g_mod[8192 * 256];
__device__ float g_sp[8 * 1024];             // dense-gate logits -> softmax in place

// ---------------------------------------------------------------------------
// NN GEMM: C[M,N] = A[M,K] @ B[K,N] (+ bias), all row-major.
// BM=64, BN=128, BK=16, 256 threads, 4x8 per-thread microtile.
// Requires M%64==0, N%128==0, K%16==0 (true for all uses here).
// ---------------------------------------------------------------------------
__global__ void gemm_nn_kernel(const float* __restrict__ A, const float* __restrict__ Bm,
                               const float* __restrict__ bias, float* __restrict__ C,
                               int M, int N, int K) {
    __shared__ float As[16][64];
    __shared__ float Bs[16][128];
    const int tid = threadIdx.x;
    const int bm = blockIdx.y * 64;
    const int bn = blockIdx.x * 128;
    const int ty = tid >> 4;         // 0..15 -> rows ty*4..
    const int tx = tid & 15;         // 0..15 -> cols tx*8..

    float acc[4][8];
#pragma unroll
    for (int i = 0; i < 4; i++)
#pragma unroll
        for (int j = 0; j < 8; j++) acc[i][j] = 0.f;

    for (int k0 = 0; k0 < K; k0 += 16) {
#pragma unroll
        for (int i = 0; i < 4; i++) {              // A tile 64x16, coalesced
            int idx = tid + i * 256;
            int r = idx >> 4, c = idx & 15;
            As[c][r] = A[(size_t)(bm + r) * K + (k0 + c)];
        }
#pragma unroll
        for (int i = 0; i < 8; i++) {              // B tile 16x128, coalesced
            int idx = tid + i * 256;
            int r = idx >> 7, c = idx & 127;
            Bs[r][c] = Bm[(size_t)(k0 + r) * N + (bn + c)];
        }
        __syncthreads();
#pragma unroll
        for (int k = 0; k < 16; k++) {
            float ra[4], rb[8];
#pragma unroll
            for (int i = 0; i < 4; i++) ra[i] = As[k][ty * 4 + i];
#pragma unroll
            for (int j = 0; j < 8; j++) rb[j] = Bs[k][tx * 8 + j];
#pragma unroll
            for (int i = 0; i < 4; i++)
#pragma unroll
                for (int j = 0; j < 8; j++) acc[i][j] += ra[i] * rb[j];
        }
        __syncthreads();
    }

#pragma unroll
    for (int i = 0; i < 4; i++) {
        size_t row = (size_t)(bm + ty * 4 + i);
#pragma unroll
        for (int j = 0; j < 8; j++) {
            int col = bn + tx * 8 + j;
            float v = acc[i][j];
            if (bias) v += bias[col];
            C[row * N + col] = v;
        }
    }
}

// ---------------------------------------------------------------------------
// NT GEMM: C[M,N] = A[M,K] @ B[N,K]^T  (for S = theta @ phi^T).
// BM=BN=128, BK=16, 256 threads, 8x8 microtile. M,N%128==0, K%16==0.
// ---------------------------------------------------------------------------
__global__ void gemm_nt_kernel(const float* __restrict__ A, const float* __restrict__ Bm,
                               float* __restrict__ C, int M, int N, int K) {
    __shared__ float As[16][128];
    __shared__ float Bs[16][128];
    const int tid = threadIdx.x;
    const int bm = blockIdx.y * 128;
    const int bn = blockIdx.x * 128;
    const int ty = tid >> 4;
    const int tx = tid & 15;

    float acc[8][8];
#pragma unroll
    for (int i = 0; i < 8; i++)
#pragma unroll
        for (int j = 0; j < 8; j++) acc[i][j] = 0.f;

    for (int k0 = 0; k0 < K; k0 += 16) {
#pragma unroll
        for (int i = 0; i < 8; i++) {
            int idx = tid + i * 256;
            int r = idx >> 4, c = idx & 15;
            As[c][r] = A[(size_t)(bm + r) * K + (k0 + c)];
            Bs[c][r] = Bm[(size_t)(bn + r) * K + (k0 + c)];
        }
        __syncthreads();
#pragma unroll
        for (int k = 0; k < 16; k++) {
            float ra[8], rb[8];
#pragma unroll
            for (int i = 0; i < 8; i++) ra[i] = As[k][ty * 8 + i];
#pragma unroll
            for (int j = 0; j < 8; j++) rb[j] = Bs[k][tx * 8 + j];
#pragma unroll
            for (int i = 0; i < 8; i++)
#pragma unroll
                for (int j = 0; j < 8; j++) acc[i][j] += ra[i] * rb[j];
        }
        __syncthreads();
    }

#pragma unroll
    for (int i = 0; i < 8; i++) {
        size_t row = (size_t)(bm + ty * 8 + i);
#pragma unroll
        for (int j = 0; j < 8; j++)
            C[row * N + (bn + tx * 8 + j)] = acc[i][j];
    }
}

// ---------------------------------------------------------------------------
// Row softmax over S (8192 cols per row), one block per row, in place.
// ---------------------------------------------------------------------------
__global__ void softmax_rows_kernel(float* __restrict__ S) {
    __shared__ float buf[8192];   // 32 KB
    __shared__ float red[256];
    const int tid = threadIdx.x;
    const size_t base = (size_t)blockIdx.x * 8192;

    float m = -1e30f;
    for (int j = tid; j < 8192; j += 256) {
        float v = S[base + j];
        buf[j] = v;
        m = fmaxf(m, v);
    }
    red[tid] = m;
    __syncthreads();
    for (int s = 128; s > 0; s >>= 1) {
        if (tid < s) red[tid] = fmaxf(red[tid], red[tid + s]);
        __syncthreads();
    }
    m = red[0];
    __syncthreads();

    float sum = 0.f;
    for (int j = tid; j < 8192; j += 256) {
        float e = __expf(buf[j] - m);
        buf[j] = e;
        sum += e;
    }
    red[tid] = sum;
    __syncthreads();
    for (int s = 128; s > 0; s >>= 1) {
        if (tid < s) red[tid] += red[tid + s];
        __syncthreads();
    }
    float inv = 1.f / red[0];
    for (int j = tid; j < 8192; j += 256)
        S[base + j] = buf[j] * inv;
}

// ---------------------------------------------------------------------------
// Dense spatial gate: logits[b][j] = sum_k x[b][k] * W_dense[k][j] (+ b_dense).
// K split across blocks (KC=512), partials combined with atomicAdd. W_dense
// (1 GB) read exactly once, fully coalesced along j.
// ---------------------------------------------------------------------------
__global__ void init_sp_kernel(const float* __restrict__ bd) {
    int i = blockIdx.x * 256 + threadIdx.x;
    if (i < 8 * 1024) g_sp[i] = bd[i & 1023];
}

__global__ void dense_gate_kernel(const float* __restrict__ x, const float* __restrict__ Wd) {
    __shared__ float xs[8][512];  // 16 KB
    const int tid = threadIdx.x;
    const int k0 = blockIdx.x * 512;

    for (int idx = tid; idx < 8 * 512; idx += 256) {
        int b = idx >> 9, kk = idx & 511;
        xs[b][kk] = x[(size_t)b * 262144 + (k0 + kk)];
    }
    __syncthreads();

    float acc[8][4];
#pragma unroll
    for (int b = 0; b < 8; b++)
#pragma unroll
        for (int q = 0; q < 4; q++) acc[b][q] = 0.f;

    for (int kk = 0; kk < 512; kk++) {
        const float* Wr = Wd + (size_t)(k0 + kk) * 1024 + tid;
        float w0 = Wr[0], w1 = Wr[256], w2 = Wr[512], w3 = Wr[768];
#pragma unroll
        for (int b = 0; b < 8; b++) {
            float xb = xs[b][kk];
            acc[b][0] += xb * w0;
            acc[b][1] += xb * w1;
            acc[b][2] += xb * w2;
            acc[b][3] += xb * w3;
        }
    }
#pragma unroll
    for (int b = 0; b < 8; b++)
#pragma unroll
        for (int q = 0; q < 4; q++)
            atomicAdd(&g_sp[b * 1024 + tid + q * 256], acc[b][q]);
}

__global__ void softmax_sp_kernel() {
    __shared__ float buf[1024];
    __shared__ float red[256];
    const int tid = threadIdx.x;
    const int base = blockIdx.x * 1024;

    float m = -1e30f;
    for (int j = tid; j < 1024; j += 256) {
        float v = g_sp[base + j];
        buf[j] = v;
        m = fmaxf(m, v);
    }
    red[tid] = m;
    __syncthreads();
    for (int s = 128; s > 0; s >>= 1) {
        if (tid < s) red[tid] = fmaxf(red[tid], red[tid + s]);
        __syncthreads();
    }
    m = red[0];
    __syncthreads();

    float sum = 0.f;
    for (int j = tid; j < 1024; j += 256) {
        float e = __expf(buf[j] - m);
        buf[j] = e;
        sum += e;
    }
    red[tid] = sum;
    __syncthreads();
    for (int s = 128; s > 0; s >>= 1) {
        if (tid < s) red[tid] += red[tid + s];
        __syncthreads();
    }
    float inv = 1.f / red[0];
    for (int j = tid; j < 1024; j += 256)
        g_sp[base + j] = buf[j] * inv;
}

// out = mod_attention * sp + x   (g_mod shares x's linear layout)
__global__ void final_kernel(const float* __restrict__ x, float* __restrict__ out) {
    int i = blockIdx.x * 256 + threadIdx.x;   // grid covers exactly 8192*256 = 2097152
    out[i] = g_mod[i] * g_sp[i >> 8] + x[i];
}

// ---------------------------------------------------------------------------
extern "C" void kernel_launch(void* const* d_in, const int* in_sizes, int n_in,
                              void* d_out, int out_size) {
    const float* x  = (const float*)d_in[0];
    const float* Wt = (const float*)d_in[1];
    const float* bt = (const float*)d_in[2];
    const float* Wp = (const float*)d_in[3];
    const float* bp = (const float*)d_in[4];
    const float* Wa = (const float*)d_in[5];
    const float* ba = (const float*)d_in[6];
    const float* Wm = (const float*)d_in[7];
    const float* Wd = (const float*)d_in[8];
    const float* bd = (const float*)d_in[9];
    float* out = (float*)d_out;

    float *p_theta, *p_phi, *p_alpha, *p_S, *p_av, *p_mod;
    cudaGetSymbolAddress((void**)&p_theta, g_theta);
    cudaGetSymbolAddress((void**)&p_phi,   g_phi);
    cudaGetSymbolAddress((void**)&p_alpha, g_alpha);
    cudaGetSymbolAddress((void**)&p_S,     g_S);
    cudaGetSymbolAddress((void**)&p_av,    g_av);
    cudaGetSymbolAddress((void**)&p_mod,   g_mod);

    // Projections: [8192,256] @ [256,128] + bias
    gemm_nn_kernel<<<dim3(1, 128), 256>>>(x, Wt, bt, p_theta, 8192, 128, 256);
    gemm_nn_kernel<<<dim3(1, 128), 256>>>(x, Wp, bp, p_phi,   8192, 128, 256);
    gemm_nn_kernel<<<dim3(1, 128), 256>>>(x, Wa, ba, p_alpha, 8192, 128, 256);

    // S = theta @ phi^T : [8192,8192]
    gemm_nt_kernel<<<dim3(64, 64), 256>>>(p_theta, p_phi, p_S, 8192, 8192, 128);

    // row softmax (in place)
    softmax_rows_kernel<<<8192, 256>>>(p_S);

    // attn @ alpha : [8192,128]
    gemm_nn_kernel<<<dim3(1, 128), 256>>>(p_S, p_alpha, nullptr, p_av, 8192, 128, 8192);

    // mod = av @ W_mask : [8192,256]
    gemm_nn_kernel<<<dim3(2, 128), 256>>>(p_av, Wm, nullptr, p_mod, 8192, 256, 128);

    // dense spatial gate
    init_sp_kernel<<<32, 256>>>(bd);
    dense_gate_kernel<<<512, 256>>>(x, Wd);
    softmax_sp_kernel<<<8, 256>>>();

    // final elementwise
    final_kernel<<<8192, 256>>>(x, out);
}

// round 2
// speedup vs baseline: 3.0865x; 3.0865x over previous
#include <cuda_runtime.h>
#include <cuda_bf16.h>
#include <cstdint>

// Shapes fixed: B=8, H=W=32, C=256 -> NTOK=8192, C2=128, HW=1024, Kdense=262144.

__device__ __nv_bfloat16 g_thb[8192 * 128];           // theta bf16 [m][k]
__device__ __nv_bfloat16 g_phb[8192 * 128];           // phi   bf16 [n][k]
__device__ __nv_bfloat16 g_alb[128 * 8192];           // alpha bf16 TRANSPOSED [c2][token]
__device__ __nv_bfloat16 g_Sb[(size_t)8192 * 8192];   // 128 MB logits/probs bf16
__device__ float g_av[8192 * 128];
__device__ float g_mod[8192 * 256];
__device__ float g_sp[8 * 1024];

// ---------------------------------------------------------------------------
// helpers
// ---------------------------------------------------------------------------
__device__ __forceinline__ void cp16(void* smem, const void* g) {
    uint32_t s = (uint32_t)__cvta_generic_to_shared(smem);
    asm volatile("cp.async.cg.shared.global [%0], [%1], 16;" :: "r"(s), "l"(g));
}
__device__ __forceinline__ void cp_commit() { asm volatile("cp.async.commit_group;"); }

__device__ __forceinline__ void ldsm_x4(uint32_t& r0, uint32_t& r1, uint32_t& r2, uint32_t& r3,
                                        const void* p) {
    uint32_t a = (uint32_t)__cvta_generic_to_shared(p);
    asm volatile("ldmatrix.sync.aligned.m8n8.x4.shared.b16 {%0,%1,%2,%3}, [%4];"
                 : "=r"(r0), "=r"(r1), "=r"(r2), "=r"(r3) : "r"(a));
}
__device__ __forceinline__ void mma16816(float& c0, float& c1, float& c2, float& c3,
                                         uint32_t a0, uint32_t a1, uint32_t a2, uint32_t a3,
                                         uint32_t b0, uint32_t b1) {
    asm volatile("mma.sync.aligned.m16n8k16.row.col.f32.bf16.bf16.f32 "
                 "{%0,%1,%2,%3},{%4,%5,%6,%7},{%8,%9},{%0,%1,%2,%3};"
                 : "+f"(c0), "+f"(c1), "+f"(c2), "+f"(c3)
                 : "r"(a0), "r"(a1), "r"(a2), "r"(a3), "r"(b0), "r"(b1));
}

// ---------------------------------------------------------------------------
// bf16 NT GEMM (tensor cores): C[M,N] = A[M,K] @ B[N,K]^T
// A row-major [m][k], B row-major [n][k] (== col-major k x n, matches mma B frag).
// BM = MFRAGS*32 (2 warps in m), BN=128 (4 warps in n), BK=32, 256 threads.
// OUTBF: 1 -> bf16 C, 0 -> fp32 C.
// ---------------------------------------------------------------------------
template<int MFRAGS, int OUTBF>
__global__ void mma_nt_kernel(const __nv_bfloat16* __restrict__ A,
                              const __nv_bfloat16* __restrict__ B,
                              __nv_bfloat16* __restrict__ Cb,
                              float* __restrict__ Cf,
                              int M, int N, int K) {
    constexpr int BM = MFRAGS * 32;
    constexpr int BK = 32;
    constexpr int LD = 40;           // smem row stride (elements), pad kills ldsm conflicts

    __shared__ __align__(16) __nv_bfloat16 As[2][BM * LD];
    __shared__ __align__(16) __nv_bfloat16 Bs[2][128 * LD];

    const int tid = threadIdx.x;
    const int lane = tid & 31;
    const int warp = tid >> 5;
    const int wm = warp & 1;         // 2 warps in m
    const int wn = warp >> 1;        // 4 warps in n
    const int bm = blockIdx.y * BM;
    const int bn = blockIdx.x * 128;

    float acc[MFRAGS][4][4];
#pragma unroll
    for (int i = 0; i < MFRAGS; i++)
#pragma unroll
        for (int j = 0; j < 4; j++)
#pragma unroll
            for (int q = 0; q < 4; q++) acc[i][j][q] = 0.f;

    const int nT = K / BK;

    auto issue = [&](int kt, int buf) {
        const int k0 = kt * BK;
#pragma unroll
        for (int i = tid; i < BM * 4; i += 256) {
            int r = i >> 2, c = i & 3;
            cp16(&As[buf][r * LD + c * 8], A + (size_t)(bm + r) * K + k0 + c * 8);
        }
#pragma unroll
        for (int i = tid; i < 512; i += 256) {
            int r = i >> 2, c = i & 3;
            cp16(&Bs[buf][r * LD + c * 8], B + (size_t)(bn + r) * K + k0 + c * 8);
        }
        cp_commit();
    };

    issue(0, 0);

    for (int kt = 0; kt < nT; kt++) {
        const int buf = kt & 1;
        if (kt + 1 < nT) {
            issue(kt + 1, (kt + 1) & 1);
            asm volatile("cp.async.wait_group 1;");
        } else {
            asm volatile("cp.async.wait_group 0;");
        }
        __syncthreads();

#pragma unroll
        for (int ks = 0; ks < 2; ks++) {
            uint32_t a[MFRAGS][4];
#pragma unroll
            for (int i = 0; i < MFRAGS; i++) {
                const __nv_bfloat16* p = &As[buf][(wm * (MFRAGS * 16) + i * 16 + (lane & 15)) * LD
                                                 + ks * 16 + (lane >> 4) * 8];
                ldsm_x4(a[i][0], a[i][1], a[i][2], a[i][3], p);
            }
            uint32_t b[2][4];
#pragma unroll
            for (int j2 = 0; j2 < 2; j2++) {
                const __nv_bfloat16* p = &Bs[buf][(wn * 32 + j2 * 16 + (lane & 7) + (lane >> 4) * 8) * LD
                                                  + ks * 16 + ((lane >> 3) & 1) * 8];
                ldsm_x4(b[j2][0], b[j2][1], b[j2][2], b[j2][3], p);
            }
#pragma unroll
            for (int i = 0; i < MFRAGS; i++)
#pragma unroll
                for (int j = 0; j < 4; j++) {
                    const int j2 = j >> 1;
                    const int o = (j & 1) * 2;
                    mma16816(acc[i][j][0], acc[i][j][1], acc[i][j][2], acc[i][j][3],
                             a[i][0], a[i][1], a[i][2], a[i][3],
                             b[j2][o], b[j2][o + 1]);
                }
        }
        __syncthreads();
    }

    // epilogue
#pragma unroll
    for (int i = 0; i < MFRAGS; i++) {
        const int r0 = bm + wm * (MFRAGS * 16) + i * 16 + (lane >> 2);
#pragma unroll
        for (int j = 0; j < 4; j++) {
            const int c = bn + wn * 32 + j * 8 + (lane & 3) * 2;
            if (OUTBF) {
                __nv_bfloat162 v0, v1;
                v0.x = __float2bfloat16_rn(acc[i][j][0]);
                v0.y = __float2bfloat16_rn(acc[i][j][1]);
                v1.x = __float2bfloat16_rn(acc[i][j][2]);
                v1.y = __float2bfloat16_rn(acc[i][j][3]);
                *reinterpret_cast<__nv_bfloat162*>(Cb + (size_t)r0 * N + c) = v0;
                *reinterpret_cast<__nv_bfloat162*>(Cb + (size_t)(r0 + 8) * N + c) = v1;
            } else {
                *reinterpret_cast<float2*>(Cf + (size_t)r0 * N + c) = make_float2(acc[i][j][0], acc[i][j][1]);
                *reinterpret_cast<float2*>(Cf + (size_t)(r0 + 8) * N + c) = make_float2(acc[i][j][2], acc[i][j][3]);
            }
        }
    }
}

// ---------------------------------------------------------------------------
// fp32 NN GEMM (small matrices): C = A[M,K] @ B[K,N] + bias.
// mode 0: fp32 out; 1: bf16 out [row][col]; 2: bf16 out TRANSPOSED [col][row], ld=ldt.
// ---------------------------------------------------------------------------
__global__ void gemm_nn_kernel(const float* __restrict__ A, const float* __restrict__ Bm,
                               const float* __restrict__ bias,
                               float* __restrict__ Cf, __nv_bfloat16* __restrict__ Cb,
                               int mode, int M, int N, int K, int ldt) {
    __shared__ float As[16][64];
    __shared__ float Bs[16][128];
    const int tid = threadIdx.x;
    const int bm = blockIdx.y * 64;
    const int bn = blockIdx.x * 128;
    const int ty = tid >> 4;
    const int tx = tid & 15;

    float acc[4][8];
#pragma unroll
    for (int i = 0; i < 4; i++)
#pragma unroll
        for (int j = 0; j < 8; j++) acc[i][j] = 0.f;

    for (int k0 = 0; k0 < K; k0 += 16) {
#pragma unroll
        for (int i = 0; i < 4; i++) {
            int idx = tid + i * 256;
            int r = idx >> 4, c = idx & 15;
            As[c][r] = A[(size_t)(bm + r) * K + (k0 + c)];
        }
#pragma unroll
        for (int i = 0; i < 8; i++) {
            int idx = tid + i * 256;
            int r = idx >> 7, c = idx & 127;
            Bs[r][c] = Bm[(size_t)(k0 + r) * N + (bn + c)];
        }
        __syncthreads();
#pragma unroll
        for (int k = 0; k < 16; k++) {
            float ra[4], rb[8];
#pragma unroll
            for (int i = 0; i < 4; i++) ra[i] = As[k][ty * 4 + i];
#pragma unroll
            for (int j = 0; j < 8; j++) rb[j] = Bs[k][tx * 8 + j];
#pragma unroll
            for (int i = 0; i < 4; i++)
#pragma unroll
                for (int j = 0; j < 8; j++) acc[i][j] += ra[i] * rb[j];
        }
        __syncthreads();
    }

#pragma unroll
    for (int i = 0; i < 4; i++) {
        const int row = bm + ty * 4 + i;
#pragma unroll
        for (int j = 0; j < 8; j++) {
            const int col = bn + tx * 8 + j;
            float v = acc[i][j];
            if (bias) v += bias[col];
            if (mode == 0)      Cf[(size_t)row * N + col] = v;
            else if (mode == 1) Cb[(size_t)row * N + col] = __float2bfloat16_rn(v);
            else                Cb[(size_t)col * ldt + row] = __float2bfloat16_rn(v);
        }
    }
}

// ---------------------------------------------------------------------------
// Row softmax over bf16 S (8192 cols), one block per row, in place.
// ---------------------------------------------------------------------------
__global__ void softmax_rows_bf16(__nv_bfloat16* __restrict__ S) {
    __shared__ float buf[8192];
    __shared__ float red[256];
    const int tid = threadIdx.x;
    const size_t base = (size_t)blockIdx.x * 8192;
    __nv_bfloat162* p = reinterpret_cast<__nv_bfloat162*>(S + base);

    float m = -1e30f;
    for (int j = tid; j < 4096; j += 256) {
        __nv_bfloat162 v = p[j];
        float a = __bfloat162float(v.x), b = __bfloat162float(v.y);
        buf[2 * j] = a;
        buf[2 * j + 1] = b;
        m = fmaxf(m, fmaxf(a, b));
    }
    red[tid] = m;
    __syncthreads();
    for (int s = 128; s > 0; s >>= 1) {
        if (tid < s) red[tid] = fmaxf(red[tid], red[tid + s]);
        __syncthreads();
    }
    m = red[0];
    __syncthreads();

    float sum = 0.f;
    for (int j = tid; j < 8192; j += 256) {
        float e = __expf(buf[j] - m);
        buf[j] = e;
        sum += e;
    }
    red[tid] = sum;
    __syncthreads();
    for (int s = 128; s > 0; s >>= 1) {
        if (tid < s) red[tid] += red[tid + s];
        __syncthreads();
    }
    const float inv = 1.f / red[0];
    for (int j = tid; j < 4096; j += 256) {
        __nv_bfloat162 v;
        v.x = __float2bfloat16_rn(buf[2 * j] * inv);
        v.y = __float2bfloat16_rn(buf[2 * j + 1] * inv);
        p[j] = v;
    }
}

// ---------------------------------------------------------------------------
// Dense spatial gate (unchanged from R1)
// ---------------------------------------------------------------------------
__global__ void init_sp_kernel(const float* __restrict__ bd) {
    int i = blockIdx.x * 256 + threadIdx.x;
    if (i < 8 * 1024) g_sp[i] = bd[i & 1023];
}

__global__ void dense_gate_kernel(const float* __restrict__ x, const float* __restrict__ Wd) {
    __shared__ float xs[8][512];
    const int tid = threadIdx.x;
    const int k0 = blockIdx.x * 512;

    for (int idx = tid; idx < 8 * 512; idx += 256) {
        int b = idx >> 9, kk = idx & 511;
        xs[b][kk] = x[(size_t)b * 262144 + (k0 + kk)];
    }
    __syncthreads();

    float acc[8][4];
#pragma unroll
    for (int b = 0; b < 8; b++)
#pragma unroll
        for (int q = 0; q < 4; q++) acc[b][q] = 0.f;

    for (int kk = 0; kk < 512; kk++) {
        const float* Wr = Wd + (size_t)(k0 + kk) * 1024 + tid;
        float w0 = Wr[0], w1 = Wr[256], w2 = Wr[512], w3 = Wr[768];
#pragma unroll
        for (int b = 0; b < 8; b++) {
            float xb = xs[b][kk];
            acc[b][0] += xb * w0;
            acc[b][1] += xb * w1;
            acc[b][2] += xb * w2;
            acc[b][3] += xb * w3;
        }
    }
#pragma unroll
    for (int b = 0; b < 8; b++)
#pragma unroll
        for (int q = 0; q < 4; q++)
            atomicAdd(&g_sp[b * 1024 + tid + q * 256], acc[b][q]);
}

__global__ void softmax_sp_kernel() {
    __shared__ float buf[1024];
    __shared__ float red[256];
    const int tid = threadIdx.x;
    const int base = blockIdx.x * 1024;

    float m = -1e30f;
    for (int j = tid; j < 1024; j += 256) {
        float v = g_sp[base + j];
        buf[j] = v;
        m = fmaxf(m, v);
    }
    red[tid] = m;
    __syncthreads();
    for (int s = 128; s > 0; s >>= 1) {
        if (tid < s) red[tid] = fmaxf(red[tid], red[tid + s]);
        __syncthreads();
    }
    m = red[0];
    __syncthreads();

    float sum = 0.f;
    for (int j = tid; j < 1024; j += 256) {
        float e = __expf(buf[j] - m);
        buf[j] = e;
        sum += e;
    }
    red[tid] = sum;
    __syncthreads();
    for (int s = 128; s > 0; s >>= 1) {
        if (tid < s) red[tid] += red[tid + s];
        __syncthreads();
    }
    const float inv = 1.f / red[0];
    for (int j = tid; j < 1024; j += 256)
        g_sp[base + j] = buf[j] * inv;
}

__global__ void final_kernel(const float* __restrict__ x, float* __restrict__ out) {
    int i = blockIdx.x * 256 + threadIdx.x;
    out[i] = g_mod[i] * g_sp[i >> 8] + x[i];
}

// ---------------------------------------------------------------------------
extern "C" void kernel_launch(void* const* d_in, const int* in_sizes, int n_in,
                              void* d_out, int out_size) {
    const float* x  = (const float*)d_in[0];
    const float* Wt = (const float*)d_in[1];
    const float* bt = (const float*)d_in[2];
    const float* Wp = (const float*)d_in[3];
    const float* bp = (const float*)d_in[4];
    const float* Wa = (const float*)d_in[5];
    const float* ba = (const float*)d_in[6];
    const float* Wm = (const float*)d_in[7];
    const float* Wd = (const float*)d_in[8];
    const float* bd = (const float*)d_in[9];
    float* out = (float*)d_out;

    __nv_bfloat16 *p_thb, *p_phb, *p_alb, *p_Sb;
    float *p_av, *p_mod;
    cudaGetSymbolAddress((void**)&p_thb, g_thb);
    cudaGetSymbolAddress((void**)&p_phb, g_phb);
    cudaGetSymbolAddress((void**)&p_alb, g_alb);
    cudaGetSymbolAddress((void**)&p_Sb,  g_Sb);
    cudaGetSymbolAddress((void**)&p_av,  g_av);
    cudaGetSymbolAddress((void**)&p_mod, g_mod);

    // Projections -> bf16 (theta, phi row-major; alpha transposed)
    gemm_nn_kernel<<<dim3(1, 128), 256>>>(x, Wt, bt, nullptr, p_thb, 1, 8192, 128, 256, 0);
    gemm_nn_kernel<<<dim3(1, 128), 256>>>(x, Wp, bp, nullptr, p_phb, 1, 8192, 128, 256, 0);
    gemm_nn_kernel<<<dim3(1, 128), 256>>>(x, Wa, ba, nullptr, p_alb, 2, 8192, 128, 256, 8192);

    // S = theta @ phi^T (bf16 tensor cores) : [8192,8192] bf16
    mma_nt_kernel<4, 1><<<dim3(64, 64), 256>>>(p_thb, p_phb, p_Sb, nullptr, 8192, 8192, 128);

    // row softmax in place (bf16 in/out, fp32 math)
    softmax_rows_bf16<<<8192, 256>>>(p_Sb);

    // av = P @ alpha = P[8192,8192] @ (albT)^T  -> fp32 [8192,128]
    mma_nt_kernel<2, 0><<<dim3(1, 128), 256>>>(p_Sb, p_alb, nullptr, p_av, 8192, 128, 8192);

    // mod = av @ W_mask : fp32 [8192,256]
    gemm_nn_kernel<<<dim3(2, 128), 256>>>(p_av, Wm, nullptr, p_mod, nullptr, 0, 8192, 256, 128, 0);

    // dense spatial gate
    init_sp_kernel<<<32, 256>>>(bd);
    dense_gate_kernel<<<512, 256>>>(x, Wd);
    softmax_sp_kernel<<<8, 256>>>();

    final_kernel<<<8192, 256>>>(x, out);
}

// round 3
// speedup vs baseline: 4.1093x; 1.3314x over previous
#include <cuda_runtime.h>
#include <cuda_bf16.h>
#include <cstdint>

// Shapes fixed: B=8, H=W=32, C=256 -> NTOK=8192, C2=128, HW=1024, Kdense=262144.

__device__ __nv_bfloat16 g_thb[8192 * 128];   // theta bf16 [m][k]
__device__ __nv_bfloat16 g_phb[8192 * 128];   // phi   bf16 [n][k]
__device__ __nv_bfloat16 g_alb[128 * 8192];   // alpha bf16 TRANSPOSED [c2][token]
__device__ float g_av[8192 * 128];
__device__ float g_mod[8192 * 256];
__device__ float g_sp[8 * 1024];

// ---------------------------------------------------------------------------
// helpers
// ---------------------------------------------------------------------------
__device__ __forceinline__ void cp16(void* smem, const void* g) {
    uint32_t s = (uint32_t)__cvta_generic_to_shared(smem);
    asm volatile("cp.async.cg.shared.global [%0], [%1], 16;" :: "r"(s), "l"(g));
}
__device__ __forceinline__ void cp_commit() { asm volatile("cp.async.commit_group;"); }

__device__ __forceinline__ void ldsm_x4(uint32_t& r0, uint32_t& r1, uint32_t& r2, uint32_t& r3,
                                        const void* p) {
    uint32_t a = (uint32_t)__cvta_generic_to_shared(p);
    asm volatile("ldmatrix.sync.aligned.m8n8.x4.shared.b16 {%0,%1,%2,%3}, [%4];"
                 : "=r"(r0), "=r"(r1), "=r"(r2), "=r"(r3) : "r"(a));
}
__device__ __forceinline__ void mma16816(float& c0, float& c1, float& c2, float& c3,
                                         uint32_t a0, uint32_t a1, uint32_t a2, uint32_t a3,
                                         uint32_t b0, uint32_t b1) {
    asm volatile("mma.sync.aligned.m16n8k16.row.col.f32.bf16.bf16.f32 "
                 "{%0,%1,%2,%3},{%4,%5,%6,%7},{%8,%9},{%0,%1,%2,%3};"
                 : "+f"(c0), "+f"(c1), "+f"(c2), "+f"(c3)
                 : "r"(a0), "r"(a1), "r"(a2), "r"(a3), "r"(b0), "r"(b1));
}

// ---------------------------------------------------------------------------
// Flash attention: av = softmax(theta @ phi^T) @ alpha, never materializing S.
// Grid: 128 CTAs, each owns BM=64 query rows, streams 64 key tiles of 128.
// 8 warps: wm = warp&1 (m halves of 32), wn = warp>>1 (4 n strips of 32).
// smem (dynamic, 176128 B):
//   th   [64][136] bf16      @ 0
//   phi  [2][128][136] bf16  @ 17408
//   alph [2][128][136] bf16  @ 87040
//   P    [64][136] bf16      @ 156672
//   red_max float[4][64]     @ 174080
//   red_sum float[4][64]     @ 175104
// ---------------------------------------------------------------------------
#define FLASH_SMEM 176128

__global__ void __launch_bounds__(256, 1)
flash_kernel(const __nv_bfloat16* __restrict__ th,
             const __nv_bfloat16* __restrict__ ph,
             const __nv_bfloat16* __restrict__ al,
             float* __restrict__ av) {
    constexpr int LD = 136;
    extern __shared__ __align__(16) char smem_raw[];
    __nv_bfloat16* th_s = (__nv_bfloat16*)(smem_raw);
    __nv_bfloat16* ph_s = (__nv_bfloat16*)(smem_raw + 17408);
    __nv_bfloat16* al_s = (__nv_bfloat16*)(smem_raw + 87040);
    __nv_bfloat16* P_s  = (__nv_bfloat16*)(smem_raw + 156672);
    float* red_max = (float*)(smem_raw + 174080);
    float* red_sum = (float*)(smem_raw + 175104);

    const int tid  = threadIdx.x;
    const int lane = tid & 31;
    const int warp = tid >> 5;
    const int wm   = warp & 1;
    const int wn   = warp >> 1;
    const int bm   = blockIdx.x * 64;

    // theta tile (once): 64 rows x 128 cols
#pragma unroll
    for (int i = tid; i < 1024; i += 256) {
        int r = i >> 4, c = i & 15;
        cp16(&th_s[r * LD + c * 8], th + (size_t)(bm + r) * 128 + c * 8);
    }

    auto issue = [&](int kt, int buf) {
        const int boff = buf * (128 * LD);
#pragma unroll
        for (int i = tid; i < 2048; i += 256) {
            int r = i >> 4, c = i & 15;
            cp16(&ph_s[boff + r * LD + c * 8], ph + (size_t)(kt * 128 + r) * 128 + c * 8);
        }
#pragma unroll
        for (int i = tid; i < 2048; i += 256) {
            int r = i >> 4, c = i & 15;
            cp16(&al_s[boff + r * LD + c * 8], al + (size_t)r * 8192 + kt * 128 + c * 8);
        }
        cp_commit();
    };

    issue(0, 0);   // group 0 holds theta + tile 0

    float o[2][4][4];
#pragma unroll
    for (int i = 0; i < 2; i++)
#pragma unroll
        for (int j = 0; j < 4; j++)
#pragma unroll
            for (int q = 0; q < 4; q++) o[i][j][q] = 0.f;
    float m_r[2][2] = {{-1e30f, -1e30f}, {-1e30f, -1e30f}};
    float l_r[2][2] = {{0.f, 0.f}, {0.f, 0.f}};

    for (int kt = 0; kt < 64; kt++) {
        const int buf = kt & 1;
        const int boff = buf * (128 * LD);
        if (kt + 1 < 64) {
            issue(kt + 1, buf ^ 1);
            asm volatile("cp.async.wait_group 1;");
        } else {
            asm volatile("cp.async.wait_group 0;");
        }
        __syncthreads();   // tiles ready; prev P fully consumed

        // ---- S = theta @ phi_tile^T ----
        float s[2][4][4];
#pragma unroll
        for (int i = 0; i < 2; i++)
#pragma unroll
            for (int j = 0; j < 4; j++)
#pragma unroll
                for (int q = 0; q < 4; q++) s[i][j][q] = 0.f;

#pragma unroll
        for (int ks = 0; ks < 8; ks++) {
            uint32_t a[2][4], b[2][4];
#pragma unroll
            for (int i = 0; i < 2; i++)
                ldsm_x4(a[i][0], a[i][1], a[i][2], a[i][3],
                        &th_s[(wm * 32 + i * 16 + (lane & 15)) * LD + ks * 16 + (lane >> 4) * 8]);
#pragma unroll
            for (int j2 = 0; j2 < 2; j2++)
                ldsm_x4(b[j2][0], b[j2][1], b[j2][2], b[j2][3],
                        &ph_s[boff + (wn * 32 + j2 * 16 + (lane & 7) + (lane >> 4) * 8) * LD
                              + ks * 16 + ((lane >> 3) & 1) * 8]);
#pragma unroll
            for (int i = 0; i < 2; i++)
#pragma unroll
                for (int j = 0; j < 4; j++) {
                    const int j2 = j >> 1, od = (j & 1) * 2;
                    mma16816(s[i][j][0], s[i][j][1], s[i][j][2], s[i][j][3],
                             a[i][0], a[i][1], a[i][2], a[i][3], b[j2][od], b[j2][od + 1]);
                }
        }

        // ---- row max (warp strip, then cross-warp) ----
#pragma unroll
        for (int i = 0; i < 2; i++) {
#pragma unroll
            for (int h = 0; h < 2; h++) {
                float tm = fmaxf(fmaxf(s[i][0][h * 2], s[i][0][h * 2 + 1]),
                                 fmaxf(s[i][1][h * 2], s[i][1][h * 2 + 1]));
                tm = fmaxf(tm, fmaxf(fmaxf(s[i][2][h * 2], s[i][2][h * 2 + 1]),
                                     fmaxf(s[i][3][h * 2], s[i][3][h * 2 + 1])));
                tm = fmaxf(tm, __shfl_xor_sync(0xffffffffu, tm, 1));
                tm = fmaxf(tm, __shfl_xor_sync(0xffffffffu, tm, 2));
                red_max[wn * 64 + wm * 32 + i * 16 + (lane >> 2) + h * 8] = tm;
            }
        }
        __syncthreads();

        // ---- p = exp(s - m_new), rescale, write P ----
#pragma unroll
        for (int i = 0; i < 2; i++) {
#pragma unroll
            for (int h = 0; h < 2; h++) {
                const int row = wm * 32 + i * 16 + (lane >> 2) + h * 8;
                float tm = fmaxf(fmaxf(red_max[row], red_max[64 + row]),
                                 fmaxf(red_max[128 + row], red_max[192 + row]));
                const float mn = fmaxf(m_r[i][h], tm);
                const float sc = __expf(m_r[i][h] - mn);
                m_r[i][h] = mn;
                float sum = 0.f;
#pragma unroll
                for (int j = 0; j < 4; j++) {
                    float p0 = __expf(s[i][j][h * 2]     - mn);
                    float p1 = __expf(s[i][j][h * 2 + 1] - mn);
                    s[i][j][h * 2] = p0;
                    s[i][j][h * 2 + 1] = p1;
                    sum += p0 + p1;
                    o[i][j][h * 2]     *= sc;
                    o[i][j][h * 2 + 1] *= sc;
                    __nv_bfloat162 v;
                    v.x = __float2bfloat16_rn(p0);
                    v.y = __float2bfloat16_rn(p1);
                    *reinterpret_cast<__nv_bfloat162*>(
                        &P_s[row * LD + wn * 32 + j * 8 + (lane & 3) * 2]) = v;
                }
                sum += __shfl_xor_sync(0xffffffffu, sum, 1);
                sum += __shfl_xor_sync(0xffffffffu, sum, 2);
                red_sum[wn * 64 + row] = sum;
                l_r[i][h] *= sc;
            }
        }
        __syncthreads();

#pragma unroll
        for (int i = 0; i < 2; i++)
#pragma unroll
            for (int h = 0; h < 2; h++) {
                const int row = wm * 32 + i * 16 + (lane >> 2) + h * 8;
                l_r[i][h] += red_sum[row] + red_sum[64 + row] + red_sum[128 + row] + red_sum[192 + row];
            }

        // ---- o += P @ alpha_tile^T ----
#pragma unroll
        for (int ks = 0; ks < 8; ks++) {
            uint32_t a[2][4], b[2][4];
#pragma unroll
            for (int i = 0; i < 2; i++)
                ldsm_x4(a[i][0], a[i][1], a[i][2], a[i][3],
                        &P_s[(wm * 32 + i * 16 + (lane & 15)) * LD + ks * 16 + (lane >> 4) * 8]);
#pragma unroll
            for (int j2 = 0; j2 < 2; j2++)
                ldsm_x4(b[j2][0], b[j2][1], b[j2][2], b[j2][3],
                        &al_s[boff + (wn * 32 + j2 * 16 + (lane & 7) + (lane >> 4) * 8) * LD
                              + ks * 16 + ((lane >> 3) & 1) * 8]);
#pragma unroll
            for (int i = 0; i < 2; i++)
#pragma unroll
                for (int j = 0; j < 4; j++) {
                    const int j2 = j >> 1, od = (j & 1) * 2;
                    mma16816(o[i][j][0], o[i][j][1], o[i][j][2], o[i][j][3],
                             a[i][0], a[i][1], a[i][2], a[i][3], b[j2][od], b[j2][od + 1]);
                }
        }
    }

    // ---- epilogue: av = o / l ----
#pragma unroll
    for (int i = 0; i < 2; i++)
#pragma unroll
        for (int h = 0; h < 2; h++) {
            const int row = bm + wm * 32 + i * 16 + (lane >> 2) + h * 8;
            const float inv = 1.f / l_r[i][h];
#pragma unroll
            for (int j = 0; j < 4; j++) {
                const int col = wn * 32 + j * 8 + (lane & 3) * 2;
                *reinterpret_cast<float2*>(av + (size_t)row * 128 + col) =
                    make_float2(o[i][j][h * 2] * inv, o[i][j][h * 2 + 1] * inv);
            }
        }
}

// ---------------------------------------------------------------------------
// Combined projections: theta/phi (row-major) + alpha (transposed), one launch.
// grid (1, 128, 3), block 256. C[M=8192, N=128] = x @ W[z] + b[z] -> bf16.
// ---------------------------------------------------------------------------
__global__ void proj_kernel(const float* __restrict__ x,
                            const float* __restrict__ W0, const float* __restrict__ W1,
                            const float* __restrict__ W2,
                            const float* __restrict__ b0, const float* __restrict__ b1,
                            const float* __restrict__ b2,
                            __nv_bfloat16* __restrict__ o0, __nv_bfloat16* __restrict__ o1,
                            __nv_bfloat16* __restrict__ o2) {
    const int z = blockIdx.z;
    const float* Bm = (z == 0) ? W0 : (z == 1) ? W1 : W2;
    const float* bias = (z == 0) ? b0 : (z == 1) ? b1 : b2;

    __shared__ float As[16][64];
    __shared__ float Bs[16][128];
    const int tid = threadIdx.x;
    const int bm = blockIdx.y * 64;
    const int ty = tid >> 4;
    const int tx = tid & 15;

    float acc[4][8];
#pragma unroll
    for (int i = 0; i < 4; i++)
#pragma unroll
        for (int j = 0; j < 8; j++) acc[i][j] = 0.f;

    for (int k0 = 0; k0 < 256; k0 += 16) {
#pragma unroll
        for (int i = 0; i < 4; i++) {
            int idx = tid + i * 256;
            int r = idx >> 4, c = idx & 15;
            As[c][r] = x[(size_t)(bm + r) * 256 + (k0 + c)];
        }
#pragma unroll
        for (int i = 0; i < 8; i++) {
            int idx = tid + i * 256;
            int r = idx >> 7, c = idx & 127;
            Bs[r][c] = Bm[(size_t)(k0 + r) * 128 + c];
        }
        __syncthreads();
#pragma unroll
        for (int k = 0; k < 16; k++) {
            float ra[4], rb[8];
#pragma unroll
            for (int i = 0; i < 4; i++) ra[i] = As[k][ty * 4 + i];
#pragma unroll
            for (int j = 0; j < 8; j++) rb[j] = Bs[k][tx * 8 + j];
#pragma unroll
            for (int i = 0; i < 4; i++)
#pragma unroll
                for (int j = 0; j < 8; j++) acc[i][j] += ra[i] * rb[j];
        }
        __syncthreads();
    }

#pragma unroll
    for (int i = 0; i < 4; i++) {
        const int row = bm + ty * 4 + i;
#pragma unroll
        for (int j = 0; j < 8; j++) {
            const int col = tx * 8 + j;
            const float v = acc[i][j] + bias[col];
            if (z == 0)      o0[(size_t)row * 128 + col] = __float2bfloat16_rn(v);
            else if (z == 1) o1[(size_t)row * 128 + col] = __float2bfloat16_rn(v);
            else             o2[(size_t)col * 8192 + row] = __float2bfloat16_rn(v);
        }
    }
}

// ---------------------------------------------------------------------------
// fp32 NN GEMM for mod = av @ W_mask : [8192,256], K=128.
// ---------------------------------------------------------------------------
__global__ void gemm_nn_kernel(const float* __restrict__ A, const float* __restrict__ Bm,
                               float* __restrict__ C, int M, int N, int K) {
    __shared__ float As[16][64];
    __shared__ float Bs[16][128];
    const int tid = threadIdx.x;
    const int bm = blockIdx.y * 64;
    const int bn = blockIdx.x * 128;
    const int ty = tid >> 4;
    const int tx = tid & 15;

    float acc[4][8];
#pragma unroll
    for (int i = 0; i < 4; i++)
#pragma unroll
        for (int j = 0; j < 8; j++) acc[i][j] = 0.f;

    for (int k0 = 0; k0 < K; k0 += 16) {
#pragma unroll
        for (int i = 0; i < 4; i++) {
            int idx = tid + i * 256;
            int r = idx >> 4, c = idx & 15;
            As[c][r] = A[(size_t)(bm + r) * K + (k0 + c)];
        }
#pragma unroll
        for (int i = 0; i < 8; i++) {
            int idx = tid + i * 256;
            int r = idx >> 7, c = idx & 127;
            Bs[r][c] = Bm[(size_t)(k0 + r) * N + (bn + c)];
        }
        __syncthreads();
#pragma unroll
        for (int k = 0; k < 16; k++) {
            float ra[4], rb[8];
#pragma unroll
            for (int i = 0; i < 4; i++) ra[i] = As[k][ty * 4 + i];
#pragma unroll
            for (int j = 0; j < 8; j++) rb[j] = Bs[k][tx * 8 + j];
#pragma unroll
            for (int i = 0; i < 4; i++)
#pragma unroll
                for (int j = 0; j < 8; j++) acc[i][j] += ra[i] * rb[j];
        }
        __syncthreads();
    }

#pragma unroll
    for (int i = 0; i < 4; i++) {
        const int row = bm + ty * 4 + i;
#pragma unroll
        for (int j = 0; j < 8; j++)
            C[(size_t)row * N + bn + tx * 8 + j] = acc[i][j];
    }
}

// ---------------------------------------------------------------------------
// Dense spatial gate, float4 loads, 1024 CTAs (K chunk 256).
// ---------------------------------------------------------------------------
__global__ void init_sp_kernel(const float* __restrict__ bd) {
    int i = blockIdx.x * 256 + threadIdx.x;
    if (i < 8 * 1024) g_sp[i] = bd[i & 1023];
}

__global__ void dense_gate_kernel(const float* __restrict__ x, const float* __restrict__ Wd) {
    __shared__ float xs[8][256];
    const int tid = threadIdx.x;
    const int k0 = blockIdx.x * 256;

#pragma unroll
    for (int idx = tid; idx < 8 * 256; idx += 256) {
        int b = idx >> 8, kk = idx & 255;
        xs[b][kk] = x[(size_t)b * 262144 + (k0 + kk)];
    }
    __syncthreads();

    float acc[8][4];
#pragma unroll
    for (int b = 0; b < 8; b++)
#pragma unroll
        for (int q = 0; q < 4; q++) acc[b][q] = 0.f;

    for (int kk = 0; kk < 256; kk++) {
        const float4 w = *reinterpret_cast<const float4*>(Wd + (size_t)(k0 + kk) * 1024 + tid * 4);
#pragma unroll
        for (int b = 0; b < 8; b++) {
            const float xb = xs[b][kk];
            acc[b][0] += xb * w.x;
            acc[b][1] += xb * w.y;
            acc[b][2] += xb * w.z;
            acc[b][3] += xb * w.w;
        }
    }
#pragma unroll
    for (int b = 0; b < 8; b++)
#pragma unroll
        for (int q = 0; q < 4; q++)
            atomicAdd(&g_sp[b * 1024 + tid * 4 + q], acc[b][q]);
}

__global__ void softmax_sp_kernel() {
    __shared__ float buf[1024];
    __shared__ float red[256];
    const int tid = threadIdx.x;
    const int base = blockIdx.x * 1024;

    float m = -1e30f;
    for (int j = tid; j < 1024; j += 256) {
        float v = g_sp[base + j];
        buf[j] = v;
        m = fmaxf(m, v);
    }
    red[tid] = m;
    __syncthreads();
    for (int s = 128; s > 0; s >>= 1) {
        if (tid < s) red[tid] = fmaxf(red[tid], red[tid + s]);
        __syncthreads();
    }
    m = red[0];
    __syncthreads();

    float sum = 0.f;
    for (int j = tid; j < 1024; j += 256) {
        float e = __expf(buf[j] - m);
        buf[j] = e;
        sum += e;
    }
    red[tid] = sum;
    __syncthreads();
    for (int s = 128; s > 0; s >>= 1) {
        if (tid < s) red[tid] += red[tid + s];
        __syncthreads();
    }
    const float inv = 1.f / red[0];
    for (int j = tid; j < 1024; j += 256)
        g_sp[base + j] = buf[j] * inv;
}

__global__ void final_kernel(const float* __restrict__ x, float* __restrict__ out) {
    int i = blockIdx.x * 256 + threadIdx.x;
    out[i] = g_mod[i] * g_sp[i >> 8] + x[i];
}

// ---------------------------------------------------------------------------
extern "C" void kernel_launch(void* const* d_in, const int* in_sizes, int n_in,
                              void* d_out, int out_size) {
    const float* x  = (const float*)d_in[0];
    const float* Wt = (const float*)d_in[1];
    const float* bt = (const float*)d_in[2];
    const float* Wp = (const float*)d_in[3];
    const float* bp = (const float*)d_in[4];
    const float* Wa = (const float*)d_in[5];
    const float* ba = (const float*)d_in[6];
    const float* Wm = (const float*)d_in[7];
    const float* Wd = (const float*)d_in[8];
    const float* bd = (const float*)d_in[9];
    float* out = (float*)d_out;

    __nv_bfloat16 *p_thb, *p_phb, *p_alb;
    float *p_av, *p_mod;
    cudaGetSymbolAddress((void**)&p_thb, g_thb);
    cudaGetSymbolAddress((void**)&p_phb, g_phb);
    cudaGetSymbolAddress((void**)&p_alb, g_alb);
    cudaGetSymbolAddress((void**)&p_av,  g_av);
    cudaGetSymbolAddress((void**)&p_mod, g_mod);

    cudaFuncSetAttribute(flash_kernel, cudaFuncAttributeMaxDynamicSharedMemorySize, FLASH_SMEM);

    // Projections -> bf16 (theta, phi row-major; alpha transposed), one launch
    proj_kernel<<<dim3(1, 128, 3), 256>>>(x, Wt, Wp, Wa, bt, bp, ba, p_thb, p_phb, p_alb);

    // Fused attention: av = softmax(theta phi^T) alpha
    flash_kernel<<<128, 256, FLASH_SMEM>>>(p_thb, p_phb, p_alb, p_av);

    // mod = av @ W_mask : fp32 [8192,256]
    gemm_nn_kernel<<<dim3(2, 128), 256>>>(p_av, Wm, p_mod, 8192, 256, 128);

    // dense spatial gate
    init_sp_kernel<<<32, 256>>>(bd);
    dense_gate_kernel<<<1024, 256>>>(x, Wd);
    softmax_sp_kernel<<<8, 256>>>();

    final_kernel<<<8192, 256>>>(x, out);
}

// round 4
// speedup vs baseline: 4.9129x; 1.1955x over previous
#include <cuda_runtime.h>
#include <cuda_bf16.h>
#include <cstdint>

// Shapes fixed: B=8, H=W=32, C=256 -> NTOK=8192, C2=128, HW=1024, Kdense=262144.

__device__ __nv_bfloat16 g_thb[8192 * 128];   // theta bf16 [m][k]
__device__ __nv_bfloat16 g_phb[8192 * 128];   // phi   bf16 [n][k]
__device__ __nv_bfloat16 g_alb[128 * 8192];   // alpha bf16 TRANSPOSED [c2][token]
__device__ float g_op[2 * 8192 * 128];        // split-K partial O (unnormalized)
__device__ float g_m[2 * 8192];               // split-K row max
__device__ float g_l[2 * 8192];               // split-K row sum
__device__ float g_av[8192 * 128];
__device__ float g_mod[8192 * 256];
__device__ float g_sp[8 * 1024];

// ---------------------------------------------------------------------------
__device__ __forceinline__ void cp16(void* smem, const void* g) {
    uint32_t s = (uint32_t)__cvta_generic_to_shared(smem);
    asm volatile("cp.async.cg.shared.global [%0], [%1], 16;" :: "r"(s), "l"(g));
}
__device__ __forceinline__ void cp_commit() { asm volatile("cp.async.commit_group;"); }

__device__ __forceinline__ void ldsm_x4(uint32_t& r0, uint32_t& r1, uint32_t& r2, uint32_t& r3,
                                        const void* p) {
    uint32_t a = (uint32_t)__cvta_generic_to_shared(p);
    asm volatile("ldmatrix.sync.aligned.m8n8.x4.shared.b16 {%0,%1,%2,%3}, [%4];"
                 : "=r"(r0), "=r"(r1), "=r"(r2), "=r"(r3) : "r"(a));
}
__device__ __forceinline__ void mma16816(float& c0, float& c1, float& c2, float& c3,
                                         uint32_t a0, uint32_t a1, uint32_t a2, uint32_t a3,
                                         uint32_t b0, uint32_t b1) {
    asm volatile("mma.sync.aligned.m16n8k16.row.col.f32.bf16.bf16.f32 "
                 "{%0,%1,%2,%3},{%4,%5,%6,%7},{%8,%9},{%0,%1,%2,%3};"
                 : "+f"(c0), "+f"(c1), "+f"(c2), "+f"(c3)
                 : "r"(a0), "r"(a1), "r"(a2), "r"(a3), "r"(b0), "r"(b1));
}
__device__ __forceinline__ uint32_t packbf2(float lo, float hi) {
    __nv_bfloat162 v;
    v.x = __float2bfloat16_rn(lo);
    v.y = __float2bfloat16_rn(hi);
    return *reinterpret_cast<uint32_t*>(&v);
}

// ---------------------------------------------------------------------------
// Flash attention, FA2-style: BM=128 rows/CTA, 8 warps x 16 rows, register P,
// warp-local softmax stats, 2-way key split. grid = 128 (64 m-tiles x 2 splits).
// smem: th[128*136] @0, ph[2][128*136] @34816, al[2][128*136] @104448 = 174080 B
// ---------------------------------------------------------------------------
#define FLASH_SMEM 174080

__global__ void __launch_bounds__(256, 1)
flash2_kernel(const __nv_bfloat16* __restrict__ th,
              const __nv_bfloat16* __restrict__ ph,
              const __nv_bfloat16* __restrict__ al,
              float* __restrict__ o_part, float* __restrict__ m_part,
              float* __restrict__ l_part) {
    constexpr int LD = 136;
    extern __shared__ __align__(16) char smem_raw[];
    __nv_bfloat16* th_s = (__nv_bfloat16*)(smem_raw);
    __nv_bfloat16* ph_s = (__nv_bfloat16*)(smem_raw + 34816);
    __nv_bfloat16* al_s = (__nv_bfloat16*)(smem_raw + 104448);

    const int tid  = threadIdx.x;
    const int lane = tid & 31;
    const int warp = tid >> 5;
    const int mtile = blockIdx.x >> 1;
    const int split = blockIdx.x & 1;
    const int bm = mtile * 128;
    const int kbase = split * 32;   // first key tile

    // theta tile 128x128 (part of group 0)
#pragma unroll
    for (int i = tid; i < 2048; i += 256) {
        int r = i >> 4, c = i & 15;
        cp16(&th_s[r * LD + c * 8], th + (size_t)(bm + r) * 128 + c * 8);
    }

    auto issue = [&](int kt, int buf) {
        const int boff = buf * (128 * LD);
        const int gk = (kbase + kt) * 128;
#pragma unroll
        for (int i = tid; i < 2048; i += 256) {
            int r = i >> 4, c = i & 15;
            cp16(&ph_s[boff + r * LD + c * 8], ph + (size_t)(gk + r) * 128 + c * 8);
        }
#pragma unroll
        for (int i = tid; i < 2048; i += 256) {
            int r = i >> 4, c = i & 15;
            cp16(&al_s[boff + r * LD + c * 8], al + (size_t)r * 8192 + gk + c * 8);
        }
        cp_commit();
    };

    issue(0, 0);       // group 0 (with theta)
    issue(1, 1);       // group 1

    float o[16][4];
#pragma unroll
    for (int j = 0; j < 16; j++)
#pragma unroll
        for (int q = 0; q < 4; q++) o[j][q] = 0.f;
    float m_r[2] = {-1e30f, -1e30f};
    float l_r[2] = {0.f, 0.f};

    for (int kt = 0; kt < 32; kt++) {
        const int buf = kt & 1;
        const int boff = buf * (128 * LD);
        if (kt < 31) asm volatile("cp.async.wait_group 1;");
        else         asm volatile("cp.async.wait_group 0;");
        __syncthreads();   // tile kt visible to all warps

        // ---- S = theta @ phi_tile^T : s[16 n8-tiles][4] ----
        float s[16][4];
#pragma unroll
        for (int j = 0; j < 16; j++)
#pragma unroll
            for (int q = 0; q < 4; q++) s[j][q] = 0.f;

#pragma unroll
        for (int ks = 0; ks < 8; ks++) {
            uint32_t a0, a1, a2, a3;
            ldsm_x4(a0, a1, a2, a3,
                    &th_s[(warp * 16 + (lane & 15)) * LD + ks * 16 + (lane >> 4) * 8]);
            uint32_t b[8][4];
#pragma unroll
            for (int j2 = 0; j2 < 8; j2++)
                ldsm_x4(b[j2][0], b[j2][1], b[j2][2], b[j2][3],
                        &ph_s[boff + (j2 * 16 + (lane & 7) + (lane >> 4) * 8) * LD
                              + ks * 16 + ((lane >> 3) & 1) * 8]);
#pragma unroll
            for (int j = 0; j < 16; j++) {
                const int j2 = j >> 1, od = (j & 1) * 2;
                mma16816(s[j][0], s[j][1], s[j][2], s[j][3],
                         a0, a1, a2, a3, b[j2][od], b[j2][od + 1]);
            }
        }

        // ---- warp-local online softmax (rows owned entirely by this warp) ----
#pragma unroll
        for (int h = 0; h < 2; h++) {
            float tm = -1e30f;
#pragma unroll
            for (int j = 0; j < 16; j++)
                tm = fmaxf(tm, fmaxf(s[j][h * 2], s[j][h * 2 + 1]));
            tm = fmaxf(tm, __shfl_xor_sync(0xffffffffu, tm, 1));
            tm = fmaxf(tm, __shfl_xor_sync(0xffffffffu, tm, 2));
            const float mn = fmaxf(m_r[h], tm);
            const float sc = __expf(m_r[h] - mn);
            m_r[h] = mn;
            float sum = 0.f;
#pragma unroll
            for (int j = 0; j < 16; j++) {
                float p0 = __expf(s[j][h * 2]     - mn);
                float p1 = __expf(s[j][h * 2 + 1] - mn);
                s[j][h * 2] = p0;
                s[j][h * 2 + 1] = p1;
                sum += p0 + p1;
                o[j][h * 2]     *= sc;
                o[j][h * 2 + 1] *= sc;
            }
            sum += __shfl_xor_sync(0xffffffffu, sum, 1);
            sum += __shfl_xor_sync(0xffffffffu, sum, 2);
            l_r[h] = l_r[h] * sc + sum;
        }

        // ---- P (C-fragment) -> A-fragment, in registers ----
        uint32_t pa[8][4];
#pragma unroll
        for (int kk = 0; kk < 8; kk++) {
            pa[kk][0] = packbf2(s[2 * kk][0],     s[2 * kk][1]);
            pa[kk][1] = packbf2(s[2 * kk][2],     s[2 * kk][3]);
            pa[kk][2] = packbf2(s[2 * kk + 1][0], s[2 * kk + 1][1]);
            pa[kk][3] = packbf2(s[2 * kk + 1][2], s[2 * kk + 1][3]);
        }

        // ---- o += P @ alpha_tile^T ----
#pragma unroll
        for (int kk = 0; kk < 8; kk++) {
            uint32_t b[8][4];
#pragma unroll
            for (int j2 = 0; j2 < 8; j2++)
                ldsm_x4(b[j2][0], b[j2][1], b[j2][2], b[j2][3],
                        &al_s[boff + (j2 * 16 + (lane & 7) + (lane >> 4) * 8) * LD
                              + kk * 16 + ((lane >> 3) & 1) * 8]);
#pragma unroll
            for (int j = 0; j < 16; j++) {
                const int j2 = j >> 1, od = (j & 1) * 2;
                mma16816(o[j][0], o[j][1], o[j][2], o[j][3],
                         pa[kk][0], pa[kk][1], pa[kk][2], pa[kk][3],
                         b[j2][od], b[j2][od + 1]);
            }
        }

        __syncthreads();   // all warps done reading buf
        if (kt + 2 < 32) issue(kt + 2, buf);
    }

    // ---- epilogue: store unnormalized o + (m, l) ----
    const size_t sb = (size_t)split * 8192;
#pragma unroll
    for (int h = 0; h < 2; h++) {
        const int row = bm + warp * 16 + (lane >> 2) + 8 * h;
        m_part[sb + row] = m_r[h];
        l_part[sb + row] = l_r[h];
#pragma unroll
        for (int j = 0; j < 16; j++) {
            const int col = j * 8 + (lane & 3) * 2;
            *reinterpret_cast<float2*>(o_part + (sb + row) * 128 + col) =
                make_float2(o[j][h * 2], o[j][h * 2 + 1]);
        }
    }
}

// ---------------------------------------------------------------------------
// Merge the 2 key-splits: av = (o0*e^{m0-m} + o1*e^{m1-m}) / l
// ---------------------------------------------------------------------------
__global__ void merge_kernel(const float* __restrict__ o_part,
                             const float* __restrict__ m_part,
                             const float* __restrict__ l_part,
                             float* __restrict__ av) {
    const int t = blockIdx.x * 256 + threadIdx.x;   // 8192*64 threads
    const int row = t >> 6;
    const int col = (t & 63) * 2;
    const float m0 = m_part[row], m1 = m_part[8192 + row];
    const float l0 = l_part[row], l1 = l_part[8192 + row];
    const float m = fmaxf(m0, m1);
    const float w0 = __expf(m0 - m), w1 = __expf(m1 - m);
    const float inv = 1.f / (l0 * w0 + l1 * w1);
    const float2 a = *reinterpret_cast<const float2*>(o_part + (size_t)row * 128 + col);
    const float2 b = *reinterpret_cast<const float2*>(o_part + (size_t)(8192 + row) * 128 + col);
    *reinterpret_cast<float2*>(av + (size_t)row * 128 + col) =
        make_float2((a.x * w0 + b.x * w1) * inv, (a.y * w0 + b.y * w1) * inv);
}

// ---------------------------------------------------------------------------
// Combined projections (z=0 theta, 1 phi, 2 alpha-transposed) -> bf16.
// ---------------------------------------------------------------------------
__global__ void proj_kernel(const float* __restrict__ x,
                            const float* __restrict__ W0, const float* __restrict__ W1,
                            const float* __restrict__ W2,
                            const float* __restrict__ b0, const float* __restrict__ b1,
                            const float* __restrict__ b2,
                            __nv_bfloat16* __restrict__ o0, __nv_bfloat16* __restrict__ o1,
                            __nv_bfloat16* __restrict__ o2) {
    const int z = blockIdx.z;
    const float* Bm = (z == 0) ? W0 : (z == 1) ? W1 : W2;
    const float* bias = (z == 0) ? b0 : (z == 1) ? b1 : b2;

    __shared__ float As[16][64];
    __shared__ float Bs[16][128];
    const int tid = threadIdx.x;
    const int bm = blockIdx.y * 64;
    const int ty = tid >> 4;
    const int tx = tid & 15;

    float acc[4][8];
#pragma unroll
    for (int i = 0; i < 4; i++)
#pragma unroll
        for (int j = 0; j < 8; j++) acc[i][j] = 0.f;

    for (int k0 = 0; k0 < 256; k0 += 16) {
#pragma unroll
        for (int i = 0; i < 4; i++) {
            int idx = tid + i * 256;
            int r = idx >> 4, c = idx & 15;
            As[c][r] = x[(size_t)(bm + r) * 256 + (k0 + c)];
        }
#pragma unroll
        for (int i = 0; i < 8; i++) {
            int idx = tid + i * 256;
            int r = idx >> 7, c = idx & 127;
            Bs[r][c] = Bm[(size_t)(k0 + r) * 128 + c];
        }
        __syncthreads();
#pragma unroll
        for (int k = 0; k < 16; k++) {
            float ra[4], rb[8];
#pragma unroll
            for (int i = 0; i < 4; i++) ra[i] = As[k][ty * 4 + i];
#pragma unroll
            for (int j = 0; j < 8; j++) rb[j] = Bs[k][tx * 8 + j];
#pragma unroll
            for (int i = 0; i < 4; i++)
#pragma unroll
                for (int j = 0; j < 8; j++) acc[i][j] += ra[i] * rb[j];
        }
        __syncthreads();
    }

#pragma unroll
    for (int i = 0; i < 4; i++) {
        const int row = bm + ty * 4 + i;
#pragma unroll
        for (int j = 0; j < 8; j++) {
            const int col = tx * 8 + j;
            const float v = acc[i][j] + bias[col];
            if (z == 0)      o0[(size_t)row * 128 + col] = __float2bfloat16_rn(v);
            else if (z == 1) o1[(size_t)row * 128 + col] = __float2bfloat16_rn(v);
            else             o2[(size_t)col * 8192 + row] = __float2bfloat16_rn(v);
        }
    }
}

// ---------------------------------------------------------------------------
// fp32 NN GEMM for mod = av @ W_mask : [8192,256], K=128.
// ---------------------------------------------------------------------------
__global__ void gemm_nn_kernel(const float* __restrict__ A, const float* __restrict__ Bm,
                               float* __restrict__ C, int M, int N, int K) {
    __shared__ float As[16][64];
    __shared__ float Bs[16][128];
    const int tid = threadIdx.x;
    const int bm = blockIdx.y * 64;
    const int bn = blockIdx.x * 128;
    const int ty = tid >> 4;
    const int tx = tid & 15;

    float acc[4][8];
#pragma unroll
    for (int i = 0; i < 4; i++)
#pragma unroll
        for (int j = 0; j < 8; j++) acc[i][j] = 0.f;

    for (int k0 = 0; k0 < K; k0 += 16) {
#pragma unroll
        for (int i = 0; i < 4; i++) {
            int idx = tid + i * 256;
            int r = idx >> 4, c = idx & 15;
            As[c][r] = A[(size_t)(bm + r) * K + (k0 + c)];
        }
#pragma unroll
        for (int i = 0; i < 8; i++) {
            int idx = tid + i * 256;
            int r = idx >> 7, c = idx & 127;
            Bs[r][c] = Bm[(size_t)(k0 + r) * N + (bn + c)];
        }
        __syncthreads();
#pragma unroll
        for (int k = 0; k < 16; k++) {
            float ra[4], rb[8];
#pragma unroll
            for (int i = 0; i < 4; i++) ra[i] = As[k][ty * 4 + i];
#pragma unroll
            for (int j = 0; j < 8; j++) rb[j] = Bs[k][tx * 8 + j];
#pragma unroll
            for (int i = 0; i < 4; i++)
#pragma unroll
                for (int j = 0; j < 8; j++) acc[i][j] += ra[i] * rb[j];
        }
        __syncthreads();
    }

#pragma unroll
    for (int i = 0; i < 4; i++) {
        const int row = bm + ty * 4 + i;
#pragma unroll
        for (int j = 0; j < 8; j++)
            C[(size_t)row * N + bn + tx * 8 + j] = acc[i][j];
    }
}

// ---------------------------------------------------------------------------
// Dense spatial gate (side stream).
// ---------------------------------------------------------------------------
__global__ void init_sp_kernel(const float* __restrict__ bd) {
    int i = blockIdx.x * 256 + threadIdx.x;
    if (i < 8 * 1024) g_sp[i] = bd[i & 1023];
}

__global__ void dense_gate_kernel(const float* __restrict__ x, const float* __restrict__ Wd) {
    __shared__ float xs[8][256];
    const int tid = threadIdx.x;
    const int k0 = blockIdx.x * 256;

#pragma unroll
    for (int idx = tid; idx < 8 * 256; idx += 256) {
        int b = idx >> 8, kk = idx & 255;
        xs[b][kk] = x[(size_t)b * 262144 + (k0 + kk)];
    }
    __syncthreads();

    float acc[8][4];
#pragma unroll
    for (int b = 0; b < 8; b++)
#pragma unroll
        for (int q = 0; q < 4; q++) acc[b][q] = 0.f;

    for (int kk = 0; kk < 256; kk++) {
        const float4 w = *reinterpret_cast<const float4*>(Wd + (size_t)(k0 + kk) * 1024 + tid * 4);
#pragma unroll
        for (int b = 0; b < 8; b++) {
            const float xb = xs[b][kk];
            acc[b][0] += xb * w.x;
            acc[b][1] += xb * w.y;
            acc[b][2] += xb * w.z;
            acc[b][3] += xb * w.w;
        }
    }
#pragma unroll
    for (int b = 0; b < 8; b++)
#pragma unroll
        for (int q = 0; q < 4; q++)
            atomicAdd(&g_sp[b * 1024 + tid * 4 + q], acc[b][q]);
}

__global__ void softmax_sp_kernel() {
    __shared__ float buf[1024];
    __shared__ float red[256];
    const int tid = threadIdx.x;
    const int base = blockIdx.x * 1024;

    float m = -1e30f;
    for (int j = tid; j < 1024; j += 256) {
        float v = g_sp[base + j];
        buf[j] = v;
        m = fmaxf(m, v);
    }
    red[tid] = m;
    __syncthreads();
    for (int s = 128; s > 0; s >>= 1) {
        if (tid < s) red[tid] = fmaxf(red[tid], red[tid + s]);
        __syncthreads();
    }
    m = red[0];
    __syncthreads();

    float sum = 0.f;
    for (int j = tid; j < 1024; j += 256) {
        float e = __expf(buf[j] - m);
        buf[j] = e;
        sum += e;
    }
    red[tid] = sum;
    __syncthreads();
    for (int s = 128; s > 0; s >>= 1) {
        if (tid < s) red[tid] += red[tid + s];
        __syncthreads();
    }
    const float inv = 1.f / red[0];
    for (int j = tid; j < 1024; j += 256)
        g_sp[base + j] = buf[j] * inv;
}

__global__ void final_kernel(const float* __restrict__ x, float* __restrict__ out) {
    int i = blockIdx.x * 256 + threadIdx.x;
    out[i] = g_mod[i] * g_sp[i >> 8] + x[i];
}

// ---------------------------------------------------------------------------
extern "C" void kernel_launch(void* const* d_in, const int* in_sizes, int n_in,
                              void* d_out, int out_size) {
    const float* x  = (const float*)d_in[0];
    const float* Wt = (const float*)d_in[1];
    const float* bt = (const float*)d_in[2];
    const float* Wp = (const float*)d_in[3];
    const float* bp = (const float*)d_in[4];
    const float* Wa = (const float*)d_in[5];
    const float* ba = (const float*)d_in[6];
    const float* Wm = (const float*)d_in[7];
    const float* Wd = (const float*)d_in[8];
    const float* bd = (const float*)d_in[9];
    float* out = (float*)d_out;

    __nv_bfloat16 *p_thb, *p_phb, *p_alb;
    float *p_op, *p_m, *p_l, *p_av, *p_mod;
    cudaGetSymbolAddress((void**)&p_thb, g_thb);
    cudaGetSymbolAddress((void**)&p_phb, g_phb);
    cudaGetSymbolAddress((void**)&p_alb, g_alb);
    cudaGetSymbolAddress((void**)&p_op,  g_op);
    cudaGetSymbolAddress((void**)&p_m,   g_m);
    cudaGetSymbolAddress((void**)&p_l,   g_l);
    cudaGetSymbolAddress((void**)&p_av,  g_av);
    cudaGetSymbolAddress((void**)&p_mod, g_mod);

    static cudaStream_t s2 = nullptr;
    static cudaEvent_t evFork = nullptr, evJoin = nullptr;
    if (!s2) {
        cudaStreamCreateWithFlags(&s2, cudaStreamNonBlocking);
        cudaEventCreateWithFlags(&evFork, cudaEventDisableTiming);
        cudaEventCreateWithFlags(&evJoin, cudaEventDisableTiming);
    }

    cudaFuncSetAttribute(flash2_kernel, cudaFuncAttributeMaxDynamicSharedMemorySize, FLASH_SMEM);

    // ---- fork: dense-gate branch (depends only on x, bd) on side stream ----
    cudaEventRecord(evFork, 0);
    cudaStreamWaitEvent(s2, evFork, 0);
    init_sp_kernel<<<32, 256, 0, s2>>>(bd);
    dense_gate_kernel<<<1024, 256, 0, s2>>>(x, Wd);
    softmax_sp_kernel<<<8, 256, 0, s2>>>();
    cudaEventRecord(evJoin, s2);

    // ---- main stream: attention chain ----
    proj_kernel<<<dim3(1, 128, 3), 256>>>(x, Wt, Wp, Wa, bt, bp, ba, p_thb, p_phb, p_alb);
    flash2_kernel<<<128, 256, FLASH_SMEM>>>(p_thb, p_phb, p_alb, p_op, p_m, p_l);
    merge_kernel<<<2048, 256>>>(p_op, p_m, p_l, p_av);
    gemm_nn_kernel<<<dim3(2, 128), 256>>>(p_av, Wm, p_mod, 8192, 256, 128);

    // ---- join, then final elementwise ----
    cudaStreamWaitEvent(0, evJoin, 0);
    final_kernel<<<8192, 256>>>(x, out);
}

// round 5
// speedup vs baseline: 4.9225x; 1.0020x over previous
#include <cuda_runtime.h>
#include <cuda_bf16.h>
#include <cstdint>

// Shapes fixed: B=8, H=W=32, C=256 -> NTOK=8192, C2=128, HW=1024, Kdense=262144.

__device__ __nv_bfloat16 g_thb[8192 * 128];   // theta bf16 [m][k]
__device__ __nv_bfloat16 g_phb[8192 * 128];   // phi   bf16 [n][k]
__device__ __nv_bfloat16 g_alb[128 * 8192];   // alpha bf16 TRANSPOSED [c2][token]
__device__ float g_op[2 * 8192 * 128];        // split-K partial O (unnormalized)
__device__ float g_m[2 * 8192];               // split-K row max
__device__ float g_l[2 * 8192];               // split-K row sum
__device__ float g_av[8192 * 128];
__device__ float g_mod[8192 * 256];
__device__ float g_sp[8 * 1024];

// ---------------------------------------------------------------------------
__device__ __forceinline__ void cp16(void* smem, const void* g) {
    uint32_t s = (uint32_t)__cvta_generic_to_shared(smem);
    asm volatile("cp.async.cg.shared.global [%0], [%1], 16;" :: "r"(s), "l"(g));
}
__device__ __forceinline__ void cp_commit() { asm volatile("cp.async.commit_group;"); }

__device__ __forceinline__ void ldsm_x4(uint32_t& r0, uint32_t& r1, uint32_t& r2, uint32_t& r3,
                                        const void* p) {
    uint32_t a = (uint32_t)__cvta_generic_to_shared(p);
    asm volatile("ldmatrix.sync.aligned.m8n8.x4.shared.b16 {%0,%1,%2,%3}, [%4];"
                 : "=r"(r0), "=r"(r1), "=r"(r2), "=r"(r3) : "r"(a));
}
__device__ __forceinline__ void mma16816(float& c0, float& c1, float& c2, float& c3,
                                         uint32_t a0, uint32_t a1, uint32_t a2, uint32_t a3,
                                         uint32_t b0, uint32_t b1) {
    asm volatile("mma.sync.aligned.m16n8k16.row.col.f32.bf16.bf16.f32 "
                 "{%0,%1,%2,%3},{%4,%5,%6,%7},{%8,%9},{%0,%1,%2,%3};"
                 : "+f"(c0), "+f"(c1), "+f"(c2), "+f"(c3)
                 : "r"(a0), "r"(a1), "r"(a2), "r"(a3), "r"(b0), "r"(b1));
}
__device__ __forceinline__ uint32_t packbf2(float lo, float hi) {
    __nv_bfloat162 v;
    v.x = __float2bfloat16_rn(lo);
    v.y = __float2bfloat16_rn(hi);
    return *reinterpret_cast<uint32_t*>(&v);
}

// ---------------------------------------------------------------------------
// Flash attention, FA2-style: BM=128 rows/CTA, 8 warps x 16 rows, register P,
// warp-local softmax stats, 2-way key split. grid = 128 (64 m-tiles x 2 splits).
// smem: th[128*136] @0, ph[2][128*136] @34816, al[2][128*136] @104448 = 174080 B
// ---------------------------------------------------------------------------
#define FLASH_SMEM 174080

__global__ void __launch_bounds__(256, 1)
flash2_kernel(const __nv_bfloat16* __restrict__ th,
              const __nv_bfloat16* __restrict__ ph,
              const __nv_bfloat16* __restrict__ al,
              float* __restrict__ o_part, float* __restrict__ m_part,
              float* __restrict__ l_part) {
    constexpr int LD = 136;
    extern __shared__ __align__(16) char smem_raw[];
    __nv_bfloat16* th_s = (__nv_bfloat16*)(smem_raw);
    __nv_bfloat16* ph_s = (__nv_bfloat16*)(smem_raw + 34816);
    __nv_bfloat16* al_s = (__nv_bfloat16*)(smem_raw + 104448);

    const int tid  = threadIdx.x;
    const int lane = tid & 31;
    const int warp = tid >> 5;
    const int mtile = blockIdx.x >> 1;
    const int split = blockIdx.x & 1;
    const int bm = mtile * 128;
    const int kbase = split * 32;   // first key tile

    // theta tile 128x128 (part of group 0)
#pragma unroll
    for (int i = tid; i < 2048; i += 256) {
        int r = i >> 4, c = i & 15;
        cp16(&th_s[r * LD + c * 8], th + (size_t)(bm + r) * 128 + c * 8);
    }

    auto issue = [&](int kt, int buf) {
        const int boff = buf * (128 * LD);
        const int gk = (kbase + kt) * 128;
#pragma unroll
        for (int i = tid; i < 2048; i += 256) {
            int r = i >> 4, c = i & 15;
            cp16(&ph_s[boff + r * LD + c * 8], ph + (size_t)(gk + r) * 128 + c * 8);
        }
#pragma unroll
        for (int i = tid; i < 2048; i += 256) {
            int r = i >> 4, c = i & 15;
            cp16(&al_s[boff + r * LD + c * 8], al + (size_t)r * 8192 + gk + c * 8);
        }
        cp_commit();
    };

    issue(0, 0);       // group 0 (with theta)
    issue(1, 1);       // group 1

    float o[16][4];
#pragma unroll
    for (int j = 0; j < 16; j++)
#pragma unroll
        for (int q = 0; q < 4; q++) o[j][q] = 0.f;
    float m_r[2] = {-1e30f, -1e30f};
    float l_r[2] = {0.f, 0.f};

    for (int kt = 0; kt < 32; kt++) {
        const int buf = kt & 1;
        const int boff = buf * (128 * LD);
        if (kt < 31) asm volatile("cp.async.wait_group 1;");
        else         asm volatile("cp.async.wait_group 0;");
        __syncthreads();   // tile kt visible to all warps

        // ---- S = theta @ phi_tile^T : s[16 n8-tiles][4] ----
        float s[16][4];
#pragma unroll
        for (int j = 0; j < 16; j++)
#pragma unroll
            for (int q = 0; q < 4; q++) s[j][q] = 0.f;

#pragma unroll
        for (int ks = 0; ks < 8; ks++) {
            uint32_t a0, a1, a2, a3;
            ldsm_x4(a0, a1, a2, a3,
                    &th_s[(warp * 16 + (lane & 15)) * LD + ks * 16 + (lane >> 4) * 8]);
            uint32_t b[8][4];
#pragma unroll
            for (int j2 = 0; j2 < 8; j2++)
                ldsm_x4(b[j2][0], b[j2][1], b[j2][2], b[j2][3],
                        &ph_s[boff + (j2 * 16 + (lane & 7) + (lane >> 4) * 8) * LD
                              + ks * 16 + ((lane >> 3) & 1) * 8]);
#pragma unroll
            for (int j = 0; j < 16; j++) {
                const int j2 = j >> 1, od = (j & 1) * 2;
                mma16816(s[j][0], s[j][1], s[j][2], s[j][3],
                         a0, a1, a2, a3, b[j2][od], b[j2][od + 1]);
            }
        }

        // ---- warp-local online softmax (rows owned entirely by this warp) ----
#pragma unroll
        for (int h = 0; h < 2; h++) {
            float tm = -1e30f;
#pragma unroll
            for (int j = 0; j < 16; j++)
                tm = fmaxf(tm, fmaxf(s[j][h * 2], s[j][h * 2 + 1]));
            tm = fmaxf(tm, __shfl_xor_sync(0xffffffffu, tm, 1));
            tm = fmaxf(tm, __shfl_xor_sync(0xffffffffu, tm, 2));
            const float mn = fmaxf(m_r[h], tm);
            const float sc = __expf(m_r[h] - mn);
            m_r[h] = mn;
            float sum = 0.f;
#pragma unroll
            for (int j = 0; j < 16; j++) {
                float p0 = __expf(s[j][h * 2]     - mn);
                float p1 = __expf(s[j][h * 2 + 1] - mn);
                s[j][h * 2] = p0;
                s[j][h * 2 + 1] = p1;
                sum += p0 + p1;
                o[j][h * 2]     *= sc;
                o[j][h * 2 + 1] *= sc;
            }
            sum += __shfl_xor_sync(0xffffffffu, sum, 1);
            sum += __shfl_xor_sync(0xffffffffu, sum, 2);
            l_r[h] = l_r[h] * sc + sum;
        }

        // ---- P (C-fragment) -> A-fragment, in registers ----
        uint32_t pa[8][4];
#pragma unroll
        for (int kk = 0; kk < 8; kk++) {
            pa[kk][0] = packbf2(s[2 * kk][0],     s[2 * kk][1]);
            pa[kk][1] = packbf2(s[2 * kk][2],     s[2 * kk][3]);
            pa[kk][2] = packbf2(s[2 * kk + 1][0], s[2 * kk + 1][1]);
            pa[kk][3] = packbf2(s[2 * kk + 1][2], s[2 * kk + 1][3]);
        }

        // ---- o += P @ alpha_tile^T ----
#pragma unroll
        for (int kk = 0; kk < 8; kk++) {
            uint32_t b[8][4];
#pragma unroll
            for (int j2 = 0; j2 < 8; j2++)
                ldsm_x4(b[j2][0], b[j2][1], b[j2][2], b[j2][3],
                        &al_s[boff + (j2 * 16 + (lane & 7) + (lane >> 4) * 8) * LD
                              + kk * 16 + ((lane >> 3) & 1) * 8]);
#pragma unroll
            for (int j = 0; j < 16; j++) {
                const int j2 = j >> 1, od = (j & 1) * 2;
                mma16816(o[j][0], o[j][1], o[j][2], o[j][3],
                         pa[kk][0], pa[kk][1], pa[kk][2], pa[kk][3],
                         b[j2][od], b[j2][od + 1]);
            }
        }

        __syncthreads();   // all warps done reading buf
        if (kt + 2 < 32) issue(kt + 2, buf);
    }

    // ---- epilogue: store unnormalized o + (m, l) ----
    const size_t sb = (size_t)split * 8192;
#pragma unroll
    for (int h = 0; h < 2; h++) {
        const int row = bm + warp * 16 + (lane >> 2) + 8 * h;
        m_part[sb + row] = m_r[h];
        l_part[sb + row] = l_r[h];
#pragma unroll
        for (int j = 0; j < 16; j++) {
            const int col = j * 8 + (lane & 3) * 2;
            *reinterpret_cast<float2*>(o_part + (sb + row) * 128 + col) =
                make_float2(o[j][h * 2], o[j][h * 2 + 1]);
        }
    }
}

// ---------------------------------------------------------------------------
// Merge the 2 key-splits: av = (o0*e^{m0-m} + o1*e^{m1-m}) / l
// ---------------------------------------------------------------------------
__global__ void merge_kernel(const float* __restrict__ o_part,
                             const float* __restrict__ m_part,
                             const float* __restrict__ l_part,
                             float* __restrict__ av) {
    const int t = blockIdx.x * 256 + threadIdx.x;   // 8192*64 threads
    const int row = t >> 6;
    const int col = (t & 63) * 2;
    const float m0 = m_part[row], m1 = m_part[8192 + row];
    const float l0 = l_part[row], l1 = l_part[8192 + row];
    const float m = fmaxf(m0, m1);
    const float w0 = __expf(m0 - m), w1 = __expf(m1 - m);
    const float inv = 1.f / (l0 * w0 + l1 * w1);
    const float2 a = *reinterpret_cast<const float2*>(o_part + (size_t)row * 128 + col);
    const float2 b = *reinterpret_cast<const float2*>(o_part + (size_t)(8192 + row) * 128 + col);
    *reinterpret_cast<float2*>(av + (size_t)row * 128 + col) =
        make_float2((a.x * w0 + b.x * w1) * inv, (a.y * w0 + b.y * w1) * inv);
}

// ---------------------------------------------------------------------------
// Combined projections (z=0 theta, 1 phi, 2 alpha-transposed) -> bf16.
// ---------------------------------------------------------------------------
__global__ void proj_kernel(const float* __restrict__ x,
                            const float* __restrict__ W0, const float* __restrict__ W1,
                            const float* __restrict__ W2,
                            const float* __restrict__ b0, const float* __restrict__ b1,
                            const float* __restrict__ b2,
                            __nv_bfloat16* __restrict__ o0, __nv_bfloat16* __restrict__ o1,
                            __nv_bfloat16* __restrict__ o2) {
    const int z = blockIdx.z;
    const float* Bm = (z == 0) ? W0 : (z == 1) ? W1 : W2;
    const float* bias = (z == 0) ? b0 : (z == 1) ? b1 : b2;

    __shared__ float As[16][64];
    __shared__ float Bs[16][128];
    const int tid = threadIdx.x;
    const int bm = blockIdx.y * 64;
    const int ty = tid >> 4;
    const int tx = tid & 15;

    float acc[4][8];
#pragma unroll
    for (int i = 0; i < 4; i++)
#pragma unroll
        for (int j = 0; j < 8; j++) acc[i][j] = 0.f;

    for (int k0 = 0; k0 < 256; k0 += 16) {
#pragma unroll
        for (int i = 0; i < 4; i++) {
            int idx = tid + i * 256;
            int r = idx >> 4, c = idx & 15;
            As[c][r] = x[(size_t)(bm + r) * 256 + (k0 + c)];
        }
#pragma unroll
        for (int i = 0; i < 8; i++) {
            int idx = tid + i * 256;
            int r = idx >> 7, c = idx & 127;
            Bs[r][c] = Bm[(size_t)(k0 + r) * 128 + c];
        }
        __syncthreads();
#pragma unroll
        for (int k = 0; k < 16; k++) {
            float ra[4], rb[8];
#pragma unroll
            for (int i = 0; i < 4; i++) ra[i] = As[k][ty * 4 + i];
#pragma unroll
            for (int j = 0; j < 8; j++) rb[j] = Bs[k][tx * 8 + j];
#pragma unroll
            for (int i = 0; i < 4; i++)
#pragma unroll
                for (int j = 0; j < 8; j++) acc[i][j] += ra[i] * rb[j];
        }
        __syncthreads();
    }

#pragma unroll
    for (int i = 0; i < 4; i++) {
        const int row = bm + ty * 4 + i;
#pragma unroll
        for (int j = 0; j < 8; j++) {
            const int col = tx * 8 + j;
            const float v = acc[i][j] + bias[col];
            if (z == 0)      o0[(size_t)row * 128 + col] = __float2bfloat16_rn(v);
            else if (z == 1) o1[(size_t)row * 128 + col] = __float2bfloat16_rn(v);
            else             o2[(size_t)col * 8192 + row] = __float2bfloat16_rn(v);
        }
    }
}

// ---------------------------------------------------------------------------
// fp32 NN GEMM for mod = av @ W_mask : [8192,256], K=128.
// ---------------------------------------------------------------------------
__global__ void gemm_nn_kernel(const float* __restrict__ A, const float* __restrict__ Bm,
                               float* __restrict__ C, int M, int N, int K) {
    __shared__ float As[16][64];
    __shared__ float Bs[16][128];
    const int tid = threadIdx.x;
    const int bm = blockIdx.y * 64;
    const int bn = blockIdx.x * 128;
    const int ty = tid >> 4;
    const int tx = tid & 15;

    float acc[4][8];
#pragma unroll
    for (int i = 0; i < 4; i++)
#pragma unroll
        for (int j = 0; j < 8; j++) acc[i][j] = 0.f;

    for (int k0 = 0; k0 < K; k0 += 16) {
#pragma unroll
        for (int i = 0; i < 4; i++) {
            int idx = tid + i * 256;
            int r = idx >> 4, c = idx & 15;
            As[c][r] = A[(size_t)(bm + r) * K + (k0 + c)];
        }
#pragma unroll
        for (int i = 0; i < 8; i++) {
            int idx = tid + i * 256;
            int r = idx >> 7, c = idx & 127;
            Bs[r][c] = Bm[(size_t)(k0 + r) * N + (bn + c)];
        }
        __syncthreads();
#pragma unroll
        for (int k = 0; k < 16; k++) {
            float ra[4], rb[8];
#pragma unroll
            for (int i = 0; i < 4; i++) ra[i] = As[k][ty * 4 + i];
#pragma unroll
            for (int j = 0; j < 8; j++) rb[j] = Bs[k][tx * 8 + j];
#pragma unroll
            for (int i = 0; i < 4; i++)
#pragma unroll
                for (int j = 0; j < 8; j++) acc[i][j] += ra[i] * rb[j];
        }
        __syncthreads();
    }

#pragma unroll
    for (int i = 0; i < 4; i++) {
        const int row = bm + ty * 4 + i;
#pragma unroll
        for (int j = 0; j < 8; j++)
            C[(size_t)row * N + bn + tx * 8 + j] = acc[i][j];
    }
}

// ---------------------------------------------------------------------------
// Dense spatial gate (side stream).
// ---------------------------------------------------------------------------
__global__ void init_sp_kernel(const float* __restrict__ bd) {
    int i = blockIdx.x * 256 + threadIdx.x;
    if (i < 8 * 1024) g_sp[i] = bd[i & 1023];
}

__global__ void dense_gate_kernel(const float* __restrict__ x, const float* __restrict__ Wd) {
    __shared__ float xs[8][256];
    const int tid = threadIdx.x;
    const int k0 = blockIdx.x * 256;

#pragma unroll
    for (int idx = tid; idx < 8 * 256; idx += 256) {
        int b = idx >> 8, kk = idx & 255;
        xs[b][kk] = x[(size_t)b * 262144 + (k0 + kk)];
    }
    __syncthreads();

    float acc[8][4];
#pragma unroll
    for (int b = 0; b < 8; b++)
#pragma unroll
        for (int q = 0; q < 4; q++) acc[b][q] = 0.f;

    for (int kk = 0; kk < 256; kk++) {
        const float4 w = *reinterpret_cast<const float4*>(Wd + (size_t)(k0 + kk) * 1024 + tid * 4);
#pragma unroll
        for (int b = 0; b < 8; b++) {
            const float xb = xs[b][kk];
            acc[b][0] += xb * w.x;
            acc[b][1] += xb * w.y;
            acc[b][2] += xb * w.z;
            acc[b][3] += xb * w.w;
        }
    }
#pragma unroll
    for (int b = 0; b < 8; b++)
#pragma unroll
        for (int q = 0; q < 4; q++)
            atomicAdd(&g_sp[b * 1024 + tid * 4 + q], acc[b][q]);
}

__global__ void softmax_sp_kernel() {
    __shared__ float buf[1024];
    __shared__ float red[256];
    const int tid = threadIdx.x;
    const int base = blockIdx.x * 1024;

    float m = -1e30f;
    for (int j = tid; j < 1024; j += 256) {
        float v = g_sp[base + j];
        buf[j] = v;
        m = fmaxf(m, v);
    }
    red[tid] = m;
    __syncthreads();
    for (int s = 128; s > 0; s >>= 1) {
        if (tid < s) red[tid] = fmaxf(red[tid], red[tid + s]);
        __syncthreads();
    }
    m = red[0];
    __syncthreads();

    float sum = 0.f;
    for (int j = tid; j < 1024; j += 256) {
        float e = __expf(buf[j] - m);
        buf[j] = e;
        sum += e;
    }
    red[tid] = sum;
    __syncthreads();
    for (int s = 128; s > 0; s >>= 1) {
        if (tid < s) red[tid] += red[tid + s];
        __syncthreads();
    }
    const float inv = 1.f / red[0];
    for (int j = tid; j < 1024; j += 256)
        g_sp[base + j] = buf[j] * inv;
}

__global__ void final_kernel(const float* __restrict__ x, float* __restrict__ out) {
    int i = blockIdx.x * 256 + threadIdx.x;
    out[i] = g_mod[i] * g_sp[i >> 8] + x[i];
}

// ---------------------------------------------------------------------------
extern "C" void kernel_launch(void* const* d_in, const int* in_sizes, int n_in,
                              void* d_out, int out_size) {
    const float* x  = (const float*)d_in[0];
    const float* Wt = (const float*)d_in[1];
    const float* bt = (const float*)d_in[2];
    const float* Wp = (const float*)d_in[3];
    const float* bp = (const float*)d_in[4];
    const float* Wa = (const float*)d_in[5];
    const float* ba = (const float*)d_in[6];
    const float* Wm = (const float*)d_in[7];
    const float* Wd = (const float*)d_in[8];
    const float* bd = (const float*)d_in[9];
    float* out = (float*)d_out;

    __nv_bfloat16 *p_thb, *p_phb, *p_alb;
    float *p_op, *p_m, *p_l, *p_av, *p_mod;
    cudaGetSymbolAddress((void**)&p_thb, g_thb);
    cudaGetSymbolAddress((void**)&p_phb, g_phb);
    cudaGetSymbolAddress((void**)&p_alb, g_alb);
    cudaGetSymbolAddress((void**)&p_op,  g_op);
    cudaGetSymbolAddress((void**)&p_m,   g_m);
    cudaGetSymbolAddress((void**)&p_l,   g_l);
    cudaGetSymbolAddress((void**)&p_av,  g_av);
    cudaGetSymbolAddress((void**)&p_mod, g_mod);

    static cudaStream_t s2 = nullptr;
    static cudaEvent_t evFork = nullptr, evJoin = nullptr;
    if (!s2) {
        cudaStreamCreateWithFlags(&s2, cudaStreamNonBlocking);
        cudaEventCreateWithFlags(&evFork, cudaEventDisableTiming);
        cudaEventCreateWithFlags(&evJoin, cudaEventDisableTiming);
    }

    cudaFuncSetAttribute(flash2_kernel, cudaFuncAttributeMaxDynamicSharedMemorySize, FLASH_SMEM);

    // ---- fork: dense-gate branch (depends only on x, bd) on side stream ----
    cudaEventRecord(evFork, 0);
    cudaStreamWaitEvent(s2, evFork, 0);
    init_sp_kernel<<<32, 256, 0, s2>>>(bd);
    dense_gate_kernel<<<1024, 256, 0, s2>>>(x, Wd);
    softmax_sp_kernel<<<8, 256, 0, s2>>>();
    cudaEventRecord(evJoin, s2);

    // ---- main stream: attention chain ----
    proj_kernel<<<dim3(1, 128, 3), 256>>>(x, Wt, Wp, Wa, bt, bp, ba, p_thb, p_phb, p_alb);
    flash2_kernel<<<128, 256, FLASH_SMEM>>>(p_thb, p_phb, p_alb, p_op, p_m, p_l);
    merge_kernel<<<2048, 256>>>(p_op, p_m, p_l, p_av);
    gemm_nn_kernel<<<dim3(2, 128), 256>>>(p_av, Wm, p_mod, 8192, 256, 128);

    // ---- join, then final elementwise ----
    cudaStreamWaitEvent(0, evJoin, 0);
    final_kernel<<<8192, 256>>>(x, out);
}

// round 6
// speedup vs baseline: 6.3045x; 1.2808x over previous
#include <cuda_runtime.h>
#include <cuda_bf16.h>
#include <cstdint>

// Shapes fixed: B=8, H=W=32, C=256 -> NTOK=8192, C2=128, HW=1024, Kdense=262144.

__device__ __nv_bfloat16 g_xb[8192 * 256];    // x bf16
__device__ __nv_bfloat16 g_WtT[128 * 256];    // W_theta^T bf16 [n][k]
__device__ __nv_bfloat16 g_WpT[128 * 256];
__device__ __nv_bfloat16 g_WaT[128 * 256];
__device__ __nv_bfloat16 g_WmT[256 * 128];    // W_mask^T bf16 [n=256][k=128]
__device__ __nv_bfloat16 g_thb[8192 * 128];   // theta bf16 [m][k]
__device__ __nv_bfloat16 g_phb[8192 * 128];   // phi   bf16 [n][k]
__device__ __nv_bfloat16 g_alb[128 * 8192];   // alpha bf16 TRANSPOSED [c2][token]
__device__ float g_op[2 * 8192 * 128];        // split-K partial O (unnormalized)
__device__ float g_m[2 * 8192];
__device__ float g_l[2 * 8192];
__device__ __nv_bfloat16 g_avb[8192 * 128];   // merged av, bf16
__device__ float g_mod[8192 * 256];
__device__ float g_sp[8 * 1024];

// ---------------------------------------------------------------------------
__device__ __forceinline__ void cp16(void* smem, const void* g) {
    uint32_t s = (uint32_t)__cvta_generic_to_shared(smem);
    asm volatile("cp.async.cg.shared.global [%0], [%1], 16;" :: "r"(s), "l"(g));
}
__device__ __forceinline__ void cp_commit() { asm volatile("cp.async.commit_group;"); }

__device__ __forceinline__ void ldsm_x4(uint32_t& r0, uint32_t& r1, uint32_t& r2, uint32_t& r3,
                                        const void* p) {
    uint32_t a = (uint32_t)__cvta_generic_to_shared(p);
    asm volatile("ldmatrix.sync.aligned.m8n8.x4.shared.b16 {%0,%1,%2,%3}, [%4];"
                 : "=r"(r0), "=r"(r1), "=r"(r2), "=r"(r3) : "r"(a));
}
__device__ __forceinline__ void mma16816(float& c0, float& c1, float& c2, float& c3,
                                         uint32_t a0, uint32_t a1, uint32_t a2, uint32_t a3,
                                         uint32_t b0, uint32_t b1) {
    asm volatile("mma.sync.aligned.m16n8k16.row.col.f32.bf16.bf16.f32 "
                 "{%0,%1,%2,%3},{%4,%5,%6,%7},{%8,%9},{%0,%1,%2,%3};"
                 : "+f"(c0), "+f"(c1), "+f"(c2), "+f"(c3)
                 : "r"(a0), "r"(a1), "r"(a2), "r"(a3), "r"(b0), "r"(b1));
}
__device__ __forceinline__ uint32_t packbf2(float lo, float hi) {
    __nv_bfloat162 v;
    v.x = __float2bfloat16_rn(lo);
    v.y = __float2bfloat16_rn(hi);
    return *reinterpret_cast<uint32_t*>(&v);
}

// ---------------------------------------------------------------------------
// Input converts: x -> bf16; weights -> transposed bf16 NT layout.
// ---------------------------------------------------------------------------
__global__ void conv_x_kernel(const float* __restrict__ x, __nv_bfloat16* __restrict__ xb) {
    const int i = (blockIdx.x * 256 + threadIdx.x) * 4;   // grid 2048 -> 2M elements
    const float4 v = *reinterpret_cast<const float4*>(x + i);
    __nv_bfloat162 a, b;
    a.x = __float2bfloat16_rn(v.x); a.y = __float2bfloat16_rn(v.y);
    b.x = __float2bfloat16_rn(v.z); b.y = __float2bfloat16_rn(v.w);
    *reinterpret_cast<__nv_bfloat162*>(xb + i) = a;
    *reinterpret_cast<__nv_bfloat162*>(xb + i + 2) = b;
}

__global__ void conv_w_kernel(const float* __restrict__ Wt, const float* __restrict__ Wp,
                              const float* __restrict__ Wa, const float* __restrict__ Wm,
                              __nv_bfloat16* __restrict__ WtT, __nv_bfloat16* __restrict__ WpT,
                              __nv_bfloat16* __restrict__ WaT, __nv_bfloat16* __restrict__ WmT) {
    const int t = blockIdx.x * 256 + threadIdx.x;   // 32768 per matrix
    const int z = blockIdx.y;
    if (z < 3) {
        // W [256][128] -> WT [128][256]: WT[n*256+k] = W[k*128+n]
        const float* W = (z == 0) ? Wt : (z == 1) ? Wp : Wa;
        __nv_bfloat16* o = (z == 0) ? WtT : (z == 1) ? WpT : WaT;
        const int n = t >> 8, k = t & 255;
        o[t] = __float2bfloat16_rn(W[k * 128 + n]);
    } else {
        // Wm [128][256] -> WmT [256][128]: WmT[n*128+k] = Wm[k*256+n]
        const int n = t >> 7, k = t & 127;
        WmT[t] = __float2bfloat16_rn(Wm[k * 256 + n]);
    }
}

// ---------------------------------------------------------------------------
// Projections on tensor cores: C[8192,128] = xb @ W{z}T^T + b{z}.
// BM=128 (2 warps m x 4 frags), BN=128 (4 warps n), BK=32, K=256.
// z=0 theta row-major, z=1 phi row-major, z=2 alpha transposed [c2][token].
// ---------------------------------------------------------------------------
__global__ void __launch_bounds__(256)
proj_mma_kernel(const __nv_bfloat16* __restrict__ xb,
                const __nv_bfloat16* __restrict__ W0, const __nv_bfloat16* __restrict__ W1,
                const __nv_bfloat16* __restrict__ W2,
                const float* __restrict__ b0, const float* __restrict__ b1,
                const float* __restrict__ b2,
                __nv_bfloat16* __restrict__ o0, __nv_bfloat16* __restrict__ o1,
                __nv_bfloat16* __restrict__ o2) {
    constexpr int LD = 40;
    __shared__ __align__(16) __nv_bfloat16 As[2][128 * LD];
    __shared__ __align__(16) __nv_bfloat16 Bs[2][128 * LD];

    const int z = blockIdx.z;
    const __nv_bfloat16* B = (z == 0) ? W0 : (z == 1) ? W1 : W2;
    const float* bias = (z == 0) ? b0 : (z == 1) ? b1 : b2;

    const int tid = threadIdx.x;
    const int lane = tid & 31;
    const int warp = tid >> 5;
    const int wm = warp & 1;
    const int wn = warp >> 1;
    const int bm = blockIdx.y * 128;

    float acc[4][4][4];
#pragma unroll
    for (int i = 0; i < 4; i++)
#pragma unroll
        for (int j = 0; j < 4; j++)
#pragma unroll
            for (int q = 0; q < 4; q++) acc[i][j][q] = 0.f;

    auto issue = [&](int kt, int buf) {
        const int k0 = kt * 32;
#pragma unroll
        for (int i = tid; i < 512; i += 256) {
            int r = i >> 2, c = i & 3;
            cp16(&As[buf][r * LD + c * 8], xb + (size_t)(bm + r) * 256 + k0 + c * 8);
        }
#pragma unroll
        for (int i = tid; i < 512; i += 256) {
            int r = i >> 2, c = i & 3;
            cp16(&Bs[buf][r * LD + c * 8], B + (size_t)r * 256 + k0 + c * 8);
        }
        cp_commit();
    };

    issue(0, 0);
    for (int kt = 0; kt < 8; kt++) {
        const int buf = kt & 1;
        if (kt + 1 < 8) {
            issue(kt + 1, buf ^ 1);
            asm volatile("cp.async.wait_group 1;");
        } else {
            asm volatile("cp.async.wait_group 0;");
        }
        __syncthreads();

#pragma unroll
        for (int ks = 0; ks < 2; ks++) {
            uint32_t a[4][4], b[2][4];
#pragma unroll
            for (int i = 0; i < 4; i++)
                ldsm_x4(a[i][0], a[i][1], a[i][2], a[i][3],
                        &As[buf][(wm * 64 + i * 16 + (lane & 15)) * LD + ks * 16 + (lane >> 4) * 8]);
#pragma unroll
            for (int j2 = 0; j2 < 2; j2++)
                ldsm_x4(b[j2][0], b[j2][1], b[j2][2], b[j2][3],
                        &Bs[buf][(wn * 32 + j2 * 16 + (lane & 7) + (lane >> 4) * 8) * LD
                                 + ks * 16 + ((lane >> 3) & 1) * 8]);
#pragma unroll
            for (int i = 0; i < 4; i++)
#pragma unroll
                for (int j = 0; j < 4; j++) {
                    const int j2 = j >> 1, od = (j & 1) * 2;
                    mma16816(acc[i][j][0], acc[i][j][1], acc[i][j][2], acc[i][j][3],
                             a[i][0], a[i][1], a[i][2], a[i][3], b[j2][od], b[j2][od + 1]);
                }
        }
        __syncthreads();
    }

#pragma unroll
    for (int i = 0; i < 4; i++) {
        const int r0 = bm + wm * 64 + i * 16 + (lane >> 2);
#pragma unroll
        for (int j = 0; j < 4; j++) {
            const int c = wn * 32 + j * 8 + (lane & 3) * 2;
            const float v0 = acc[i][j][0] + bias[c];
            const float v1 = acc[i][j][1] + bias[c + 1];
            const float v2 = acc[i][j][2] + bias[c];
            const float v3 = acc[i][j][3] + bias[c + 1];
            if (z == 2) {
                o2[(size_t)c * 8192 + r0]           = __float2bfloat16_rn(v0);
                o2[(size_t)(c + 1) * 8192 + r0]     = __float2bfloat16_rn(v1);
                o2[(size_t)c * 8192 + r0 + 8]       = __float2bfloat16_rn(v2);
                o2[(size_t)(c + 1) * 8192 + r0 + 8] = __float2bfloat16_rn(v3);
            } else {
                __nv_bfloat16* o = (z == 0) ? o0 : o1;
                __nv_bfloat162 w0, w1;
                w0.x = __float2bfloat16_rn(v0); w0.y = __float2bfloat16_rn(v1);
                w1.x = __float2bfloat16_rn(v2); w1.y = __float2bfloat16_rn(v3);
                *reinterpret_cast<__nv_bfloat162*>(o + (size_t)r0 * 128 + c) = w0;
                *reinterpret_cast<__nv_bfloat162*>(o + (size_t)(r0 + 8) * 128 + c) = w1;
            }
        }
    }
}

// ---------------------------------------------------------------------------
// mod = avb @ WmT^T : [8192, 256] fp32, K=128. BM=64 (MFRAGS=2), BN=128.
// grid (2, 128).
// ---------------------------------------------------------------------------
__global__ void __launch_bounds__(256)
mod_mma_kernel(const __nv_bfloat16* __restrict__ A, const __nv_bfloat16* __restrict__ B,
               float* __restrict__ C) {
    constexpr int LD = 40;
    __shared__ __align__(16) __nv_bfloat16 As[2][64 * LD];
    __shared__ __align__(16) __nv_bfloat16 Bs[2][128 * LD];

    const int tid = threadIdx.x;
    const int lane = tid & 31;
    const int warp = tid >> 5;
    const int wm = warp & 1;
    const int wn = warp >> 1;
    const int bm = blockIdx.y * 64;
    const int bn = blockIdx.x * 128;

    float acc[2][4][4];
#pragma unroll
    for (int i = 0; i < 2; i++)
#pragma unroll
        for (int j = 0; j < 4; j++)
#pragma unroll
            for (int q = 0; q < 4; q++) acc[i][j][q] = 0.f;

    auto issue = [&](int kt, int buf) {
        const int k0 = kt * 32;
#pragma unroll
        for (int i = tid; i < 256; i += 256) {
            int r = i >> 2, c = i & 3;
            cp16(&As[buf][r * LD + c * 8], A + (size_t)(bm + r) * 128 + k0 + c * 8);
        }
#pragma unroll
        for (int i = tid; i < 512; i += 256) {
            int r = i >> 2, c = i & 3;
            cp16(&Bs[buf][r * LD + c * 8], B + (size_t)(bn + r) * 128 + k0 + c * 8);
        }
        cp_commit();
    };

    issue(0, 0);
    for (int kt = 0; kt < 4; kt++) {
        const int buf = kt & 1;
        if (kt + 1 < 4) {
            issue(kt + 1, buf ^ 1);
            asm volatile("cp.async.wait_group 1;");
        } else {
            asm volatile("cp.async.wait_group 0;");
        }
        __syncthreads();

#pragma unroll
        for (int ks = 0; ks < 2; ks++) {
            uint32_t a[2][4], b[2][4];
#pragma unroll
            for (int i = 0; i < 2; i++)
                ldsm_x4(a[i][0], a[i][1], a[i][2], a[i][3],
                        &As[buf][(wm * 32 + i * 16 + (lane & 15)) * LD + ks * 16 + (lane >> 4) * 8]);
#pragma unroll
            for (int j2 = 0; j2 < 2; j2++)
                ldsm_x4(b[j2][0], b[j2][1], b[j2][2], b[j2][3],
                        &Bs[buf][(wn * 32 + j2 * 16 + (lane & 7) + (lane >> 4) * 8) * LD
                                 + ks * 16 + ((lane >> 3) & 1) * 8]);
#pragma unroll
            for (int i = 0; i < 2; i++)
#pragma unroll
                for (int j = 0; j < 4; j++) {
                    const int j2 = j >> 1, od = (j & 1) * 2;
                    mma16816(acc[i][j][0], acc[i][j][1], acc[i][j][2], acc[i][j][3],
                             a[i][0], a[i][1], a[i][2], a[i][3], b[j2][od], b[j2][od + 1]);
                }
        }
        __syncthreads();
    }

#pragma unroll
    for (int i = 0; i < 2; i++) {
        const int r0 = bm + wm * 32 + i * 16 + (lane >> 2);
#pragma unroll
        for (int j = 0; j < 4; j++) {
            const int c = bn + wn * 32 + j * 8 + (lane & 3) * 2;
            *reinterpret_cast<float2*>(C + (size_t)r0 * 256 + c) =
                make_float2(acc[i][j][0], acc[i][j][1]);
            *reinterpret_cast<float2*>(C + (size_t)(r0 + 8) * 256 + c) =
                make_float2(acc[i][j][2], acc[i][j][3]);
        }
    }
}

// ---------------------------------------------------------------------------
// Flash attention, FA2-style (unchanged from R5).
// ---------------------------------------------------------------------------
#define FLASH_SMEM 174080

__global__ void __launch_bounds__(256, 1)
flash2_kernel(const __nv_bfloat16* __restrict__ th,
              const __nv_bfloat16* __restrict__ ph,
              const __nv_bfloat16* __restrict__ al,
              float* __restrict__ o_part, float* __restrict__ m_part,
              float* __restrict__ l_part) {
    constexpr int LD = 136;
    extern __shared__ __align__(16) char smem_raw[];
    __nv_bfloat16* th_s = (__nv_bfloat16*)(smem_raw);
    __nv_bfloat16* ph_s = (__nv_bfloat16*)(smem_raw + 34816);
    __nv_bfloat16* al_s = (__nv_bfloat16*)(smem_raw + 104448);

    const int tid  = threadIdx.x;
    const int lane = tid & 31;
    const int warp = tid >> 5;
    const int mtile = blockIdx.x >> 1;
    const int split = blockIdx.x & 1;
    const int bm = mtile * 128;
    const int kbase = split * 32;

#pragma unroll
    for (int i = tid; i < 2048; i += 256) {
        int r = i >> 4, c = i & 15;
        cp16(&th_s[r * LD + c * 8], th + (size_t)(bm + r) * 128 + c * 8);
    }

    auto issue = [&](int kt, int buf) {
        const int boff = buf * (128 * LD);
        const int gk = (kbase + kt) * 128;
#pragma unroll
        for (int i = tid; i < 2048; i += 256) {
            int r = i >> 4, c = i & 15;
            cp16(&ph_s[boff + r * LD + c * 8], ph + (size_t)(gk + r) * 128 + c * 8);
        }
#pragma unroll
        for (int i = tid; i < 2048; i += 256) {
            int r = i >> 4, c = i & 15;
            cp16(&al_s[boff + r * LD + c * 8], al + (size_t)r * 8192 + gk + c * 8);
        }
        cp_commit();
    };

    issue(0, 0);
    issue(1, 1);

    float o[16][4];
#pragma unroll
    for (int j = 0; j < 16; j++)
#pragma unroll
        for (int q = 0; q < 4; q++) o[j][q] = 0.f;
    float m_r[2] = {-1e30f, -1e30f};
    float l_r[2] = {0.f, 0.f};

    for (int kt = 0; kt < 32; kt++) {
        const int buf = kt & 1;
        const int boff = buf * (128 * LD);
        if (kt < 31) asm volatile("cp.async.wait_group 1;");
        else         asm volatile("cp.async.wait_group 0;");
        __syncthreads();

        float s[16][4];
#pragma unroll
        for (int j = 0; j < 16; j++)
#pragma unroll
            for (int q = 0; q < 4; q++) s[j][q] = 0.f;

#pragma unroll
        for (int ks = 0; ks < 8; ks++) {
            uint32_t a0, a1, a2, a3;
            ldsm_x4(a0, a1, a2, a3,
                    &th_s[(warp * 16 + (lane & 15)) * LD + ks * 16 + (lane >> 4) * 8]);
            uint32_t b[8][4];
#pragma unroll
            for (int j2 = 0; j2 < 8; j2++)
                ldsm_x4(b[j2][0], b[j2][1], b[j2][2], b[j2][3],
                        &ph_s[boff + (j2 * 16 + (lane & 7) + (lane >> 4) * 8) * LD
                              + ks * 16 + ((lane >> 3) & 1) * 8]);
#pragma unroll
            for (int j = 0; j < 16; j++) {
                const int j2 = j >> 1, od = (j & 1) * 2;
                mma16816(s[j][0], s[j][1], s[j][2], s[j][3],
                         a0, a1, a2, a3, b[j2][od], b[j2][od + 1]);
            }
        }

#pragma unroll
        for (int h = 0; h < 2; h++) {
            float tm = -1e30f;
#pragma unroll
            for (int j = 0; j < 16; j++)
                tm = fmaxf(tm, fmaxf(s[j][h * 2], s[j][h * 2 + 1]));
            tm = fmaxf(tm, __shfl_xor_sync(0xffffffffu, tm, 1));
            tm = fmaxf(tm, __shfl_xor_sync(0xffffffffu, tm, 2));
            const float mn = fmaxf(m_r[h], tm);
            const float sc = __expf(m_r[h] - mn);
            m_r[h] = mn;
            float sum = 0.f;
#pragma unroll
            for (int j = 0; j < 16; j++) {
                float p0 = __expf(s[j][h * 2]     - mn);
                float p1 = __expf(s[j][h * 2 + 1] - mn);
                s[j][h * 2] = p0;
                s[j][h * 2 + 1] = p1;
                sum += p0 + p1;
                o[j][h * 2]     *= sc;
                o[j][h * 2 + 1] *= sc;
            }
            sum += __shfl_xor_sync(0xffffffffu, sum, 1);
            sum += __shfl_xor_sync(0xffffffffu, sum, 2);
            l_r[h] = l_r[h] * sc + sum;
        }

        uint32_t pa[8][4];
#pragma unroll
        for (int kk = 0; kk < 8; kk++) {
            pa[kk][0] = packbf2(s[2 * kk][0],     s[2 * kk][1]);
            pa[kk][1] = packbf2(s[2 * kk][2],     s[2 * kk][3]);
            pa[kk][2] = packbf2(s[2 * kk + 1][0], s[2 * kk + 1][1]);
            pa[kk][3] = packbf2(s[2 * kk + 1][2], s[2 * kk + 1][3]);
        }

#pragma unroll
        for (int kk = 0; kk < 8; kk++) {
            uint32_t b[8][4];
#pragma unroll
            for (int j2 = 0; j2 < 8; j2++)
                ldsm_x4(b[j2][0], b[j2][1], b[j2][2], b[j2][3],
                        &al_s[boff + (j2 * 16 + (lane & 7) + (lane >> 4) * 8) * LD
                              + kk * 16 + ((lane >> 3) & 1) * 8]);
#pragma unroll
            for (int j = 0; j < 16; j++) {
                const int j2 = j >> 1, od = (j & 1) * 2;
                mma16816(o[j][0], o[j][1], o[j][2], o[j][3],
                         pa[kk][0], pa[kk][1], pa[kk][2], pa[kk][3],
                         b[j2][od], b[j2][od + 1]);
            }
        }

        __syncthreads();
        if (kt + 2 < 32) issue(kt + 2, buf);
    }

    const size_t sb = (size_t)split * 8192;
#pragma unroll
    for (int h = 0; h < 2; h++) {
        const int row = bm + warp * 16 + (lane >> 2) + 8 * h;
        m_part[sb + row] = m_r[h];
        l_part[sb + row] = l_r[h];
#pragma unroll
        for (int j = 0; j < 16; j++) {
            const int col = j * 8 + (lane & 3) * 2;
            *reinterpret_cast<float2*>(o_part + (sb + row) * 128 + col) =
                make_float2(o[j][h * 2], o[j][h * 2 + 1]);
        }
    }
}

// ---------------------------------------------------------------------------
// Merge splits -> bf16 av.
// ---------------------------------------------------------------------------
__global__ void merge_kernel(const float* __restrict__ o_part,
                             const float* __restrict__ m_part,
                             const float* __restrict__ l_part,
                             __nv_bfloat16* __restrict__ avb) {
    const int t = blockIdx.x * 256 + threadIdx.x;
    const int row = t >> 6;
    const int col = (t & 63) * 2;
    const float m0 = m_part[row], m1 = m_part[8192 + row];
    const float l0 = l_part[row], l1 = l_part[8192 + row];
    const float m = fmaxf(m0, m1);
    const float w0 = __expf(m0 - m), w1 = __expf(m1 - m);
    const float inv = 1.f / (l0 * w0 + l1 * w1);
    const float2 a = *reinterpret_cast<const float2*>(o_part + (size_t)row * 128 + col);
    const float2 b = *reinterpret_cast<const float2*>(o_part + (size_t)(8192 + row) * 128 + col);
    __nv_bfloat162 v;
    v.x = __float2bfloat16_rn((a.x * w0 + b.x * w1) * inv);
    v.y = __float2bfloat16_rn((a.y * w0 + b.y * w1) * inv);
    *reinterpret_cast<__nv_bfloat162*>(avb + (size_t)row * 128 + col) = v;
}

// ---------------------------------------------------------------------------
// Dense spatial gate (side stream, unchanged).
// ---------------------------------------------------------------------------
__global__ void init_sp_kernel(const float* __restrict__ bd) {
    int i = blockIdx.x * 256 + threadIdx.x;
    if (i < 8 * 1024) g_sp[i] = bd[i & 1023];
}

__global__ void dense_gate_kernel(const float* __restrict__ x, const float* __restrict__ Wd) {
    __shared__ float xs[8][256];
    const int tid = threadIdx.x;
    const int k0 = blockIdx.x * 256;

#pragma unroll
    for (int idx = tid; idx < 8 * 256; idx += 256) {
        int b = idx >> 8, kk = idx & 255;
        xs[b][kk] = x[(size_t)b * 262144 + (k0 + kk)];
    }
    __syncthreads();

    float acc[8][4];
#pragma unroll
    for (int b = 0; b < 8; b++)
#pragma unroll
        for (int q = 0; q < 4; q++) acc[b][q] = 0.f;

    for (int kk = 0; kk < 256; kk++) {
        const float4 w = *reinterpret_cast<const float4*>(Wd + (size_t)(k0 + kk) * 1024 + tid * 4);
#pragma unroll
        for (int b = 0; b < 8; b++) {
            const float xb = xs[b][kk];
            acc[b][0] += xb * w.x;
            acc[b][1] += xb * w.y;
            acc[b][2] += xb * w.z;
            acc[b][3] += xb * w.w;
        }
    }
#pragma unroll
    for (int b = 0; b < 8; b++)
#pragma unroll
        for (int q = 0; q < 4; q++)
            atomicAdd(&g_sp[b * 1024 + tid * 4 + q], acc[b][q]);
}

__global__ void softmax_sp_kernel() {
    __shared__ float buf[1024];
    __shared__ float red[256];
    const int tid = threadIdx.x;
    const int base = blockIdx.x * 1024;

    float m = -1e30f;
    for (int j = tid; j < 1024; j += 256) {
        float v = g_sp[base + j];
        buf[j] = v;
        m = fmaxf(m, v);
    }
    red[tid] = m;
    __syncthreads();
    for (int s = 128; s > 0; s >>= 1) {
        if (tid < s) red[tid] = fmaxf(red[tid], red[tid + s]);
        __syncthreads();
    }
    m = red[0];
    __syncthreads();

    float sum = 0.f;
    for (int j = tid; j < 1024; j += 256) {
        float e = __expf(buf[j] - m);
        buf[j] = e;
        sum += e;
    }
    red[tid] = sum;
    __syncthreads();
    for (int s = 128; s > 0; s >>= 1) {
        if (tid < s) red[tid] += red[tid + s];
        __syncthreads();
    }
    const float inv = 1.f / red[0];
    for (int j = tid; j < 1024; j += 256)
        g_sp[base + j] = buf[j] * inv;
}

__global__ void final_kernel(const float* __restrict__ x, float* __restrict__ out) {
    int i = blockIdx.x * 256 + threadIdx.x;
    out[i] = g_mod[i] * g_sp[i >> 8] + x[i];
}

// ---------------------------------------------------------------------------
extern "C" void kernel_launch(void* const* d_in, const int* in_sizes, int n_in,
                              void* d_out, int out_size) {
    const float* x  = (const float*)d_in[0];
    const float* Wt = (const float*)d_in[1];
    const float* bt = (const float*)d_in[2];
    const float* Wp = (const float*)d_in[3];
    const float* bp = (const float*)d_in[4];
    const float* Wa = (const float*)d_in[5];
    const float* ba = (const float*)d_in[6];
    const float* Wm = (const float*)d_in[7];
    const float* Wd = (const float*)d_in[8];
    const float* bd = (const float*)d_in[9];
    float* out = (float*)d_out;

    __nv_bfloat16 *p_xb, *p_WtT, *p_WpT, *p_WaT, *p_WmT, *p_thb, *p_phb, *p_alb, *p_avb;
    float *p_op, *p_m, *p_l, *p_mod;
    cudaGetSymbolAddress((void**)&p_xb,  g_xb);
    cudaGetSymbolAddress((void**)&p_WtT, g_WtT);
    cudaGetSymbolAddress((void**)&p_WpT, g_WpT);
    cudaGetSymbolAddress((void**)&p_WaT, g_WaT);
    cudaGetSymbolAddress((void**)&p_WmT, g_WmT);
    cudaGetSymbolAddress((void**)&p_thb, g_thb);
    cudaGetSymbolAddress((void**)&p_phb, g_phb);
    cudaGetSymbolAddress((void**)&p_alb, g_alb);
    cudaGetSymbolAddress((void**)&p_op,  g_op);
    cudaGetSymbolAddress((void**)&p_m,   g_m);
    cudaGetSymbolAddress((void**)&p_l,   g_l);
    cudaGetSymbolAddress((void**)&p_avb, g_avb);
    cudaGetSymbolAddress((void**)&p_mod, g_mod);

    static cudaStream_t s2 = nullptr;
    static cudaEvent_t evFork = nullptr, evJoin = nullptr;
    if (!s2) {
        cudaStreamCreateWithFlags(&s2, cudaStreamNonBlocking);
        cudaEventCreateWithFlags(&evFork, cudaEventDisableTiming);
        cudaEventCreateWithFlags(&evJoin, cudaEventDisableTiming);
    }

    cudaFuncSetAttribute(flash2_kernel, cudaFuncAttributeMaxDynamicSharedMemorySize, FLASH_SMEM);

    // ---- fork: dense-gate branch on side stream ----
    cudaEventRecord(evFork, 0);
    cudaStreamWaitEvent(s2, evFork, 0);
    init_sp_kernel<<<32, 256, 0, s2>>>(bd);
    dense_gate_kernel<<<1024, 256, 0, s2>>>(x, Wd);
    softmax_sp_kernel<<<8, 256, 0, s2>>>();
    cudaEventRecord(evJoin, s2);

    // ---- main stream: attention chain, all tensor-core ----
    conv_x_kernel<<<2048, 256>>>(x, p_xb);
    conv_w_kernel<<<dim3(128, 4), 256>>>(Wt, Wp, Wa, Wm, p_WtT, p_WpT, p_WaT, p_WmT);
    proj_mma_kernel<<<dim3(1, 64, 3), 256>>>(p_xb, p_WtT, p_WpT, p_WaT, bt, bp, ba,
                                             p_thb, p_phb, p_alb);
    flash2_kernel<<<128, 256, FLASH_SMEM>>>(p_thb, p_phb, p_alb, p_op, p_m, p_l);
    merge_kernel<<<2048, 256>>>(p_op, p_m, p_l, p_avb);
    mod_mma_kernel<<<dim3(2, 128), 256>>>(p_avb, p_WmT, p_mod);

    // ---- join, then final elementwise ----
    cudaStreamWaitEvent(0, evJoin, 0);
    final_kernel<<<8192, 256>>>(x, out);
}